// round 14
// baseline (speedup 1.0000x reference)
#include <cuda_runtime.h>
#include <cuda_bf16.h>
#include <cstdint>
#include <math.h>

using bf16 = __nv_bfloat16;

// ---------------- problem constants ----------------
constexpr int Bd  = 4;
constexpr int S1  = 64;
constexpr int S2  = 256;
constexpr int D   = 256;
constexpr int Hh  = 8;
constexpr int HD  = 32;
constexpr int Fd  = 1024;
constexpr int TOK = Bd * S1 * S2;     // 65536
constexpr int BN_ = Bd * S1;          // 256
constexpr int SP  = S2 + 2;           // padded time length 258

// ---------------- scratch (device globals) ----------------
__device__ bf16  g_xph[BN_ * SP * D];
__device__ bf16  g_qh [TOK * D];
__device__ bf16  g_kh [TOK * D];
__device__ bf16  g_vh [TOK * D];
__device__ bf16  g_aoh[TOK * D];
__device__ float g_s  [TOK * D];
__device__ float g_h  [TOK * D];
__device__ bf16  g_hh [TOK * D];
__device__ bf16  g_ffh[TOK * Fd];
// transposed weights (hi only)
__device__ bf16 g_wqh[D * 3 * D];
__device__ bf16 g_wkh[D * 3 * D];
__device__ bf16 g_wvh[D * D];
__device__ bf16 g_woh[D * D];
__device__ bf16 g_w1h[Fd * D];
__device__ bf16 g_w2h[D * Fd];

// ---------------- helpers ----------------
__device__ __forceinline__ uint32_t smem_to_u32(const void* p) {
    uint32_t a;
    asm("{ .reg .u64 t; cvta.to.shared.u64 t, %1; cvt.u32.u64 %0, t; }" : "=r"(a) : "l"(p));
    return a;
}
#define CP_ASYNC16(s, g) \
    asm volatile("cp.async.cg.shared.global [%0], [%1], 16;" :: "r"((uint32_t)(s)), "l"(g))
#define CP_ASYNC_COMMIT() asm volatile("cp.async.commit_group;" ::: "memory")

__device__ __forceinline__ void ldsm4(uint32_t addr, uint32_t& r0, uint32_t& r1,
                                      uint32_t& r2, uint32_t& r3) {
    asm volatile("ldmatrix.sync.aligned.m8n8.x4.shared.b16 {%0,%1,%2,%3}, [%4];"
                 : "=r"(r0), "=r"(r1), "=r"(r2), "=r"(r3) : "r"(addr));
}
__device__ __forceinline__ void ldsm4t(uint32_t addr, uint32_t& r0, uint32_t& r1,
                                       uint32_t& r2, uint32_t& r3) {
    asm volatile("ldmatrix.sync.aligned.m8n8.x4.trans.shared.b16 {%0,%1,%2,%3}, [%4];"
                 : "=r"(r0), "=r"(r1), "=r"(r2), "=r"(r3) : "r"(addr));
}
__device__ __forceinline__ void mma_bf16(float* c, const uint32_t* a, const uint32_t* b) {
    asm volatile("mma.sync.aligned.m16n8k16.row.col.f32.bf16.bf16.f32 "
                 "{%0,%1,%2,%3}, {%4,%5,%6,%7}, {%8,%9}, {%0,%1,%2,%3};"
                 : "+f"(c[0]), "+f"(c[1]), "+f"(c[2]), "+f"(c[3])
                 : "r"(a[0]), "r"(a[1]), "r"(a[2]), "r"(a[3]), "r"(b[0]), "r"(b[1]));
}
__device__ __forceinline__ float ex2(float x) {
    float y; asm("ex2.approx.f32 %0, %1;" : "=f"(y) : "f"(x)); return y;
}
__device__ __forceinline__ uint32_t pack2(bf16 a, bf16 b) {
    __nv_bfloat162 p; p.x = a; p.y = b;
    return *(uint32_t*)&p;
}
// 128B-row swizzle (BK=64): 8 16B cols, XOR by row&7 (SW128)
__device__ __forceinline__ uint32_t sw128r(int row, int c) {
    return (uint32_t)(row * 128 + ((c ^ (row & 7)) << 4));
}

// ---------------------------------------------------------------------------
// Persistent tensor-core GEMM: grid = 2*SMs CTAs loop over 128x128 tiles.
// BK=64, 1-pass bf16, 3-stage cp.async pipeline with CROSS-TILE prefetch
// (next tile's first 2 chunks issued before the epilogue -> pipeline never
// drains). Up to 3 ops per launch (tile id -> op), merging Q/K/V.
// stage (32KB): [Ah 16K][Bh 16K] (128B rows, sw128r)
// EPI: 1 = bias*scl + R -> fp32 ; 2 = bias*scl + leaky -> bf16 hi ;
//      4 = bias*scl -> bf16 hi
// ---------------------------------------------------------------------------
constexpr int GSTAGE = 32768;
constexpr int GSMEM  = 3 * GSTAGE;   // 98304

struct GOp {
    const bf16* Bh;
    const float* bias;
    float scl;
    bf16* Ch;
    float* Cf;
    const float* R;
    int ldB, Ktap, ntaps, tapbase, Nt;
};

struct TCfg {
    int rowbase, n0, m0;
    const bf16* Bh;
    int ldB, Ktap, kcpt, nch;
    const float* bias; float scl;
    bf16* Ch; float* Cf; const float* R; int Nt;
};

template<int EPI, bool CONV>
__global__ __launch_bounds__(256, 2)
void gemm_tc(const bf16* __restrict__ Ah, int ldA,
             GOp o0, GOp o1, GOp o2, int cum0, int cum1, int ntot)
{
    extern __shared__ char smem[];
    const uint32_t sbase = smem_to_u32(smem);
    const int tid = threadIdx.x, wid = tid >> 5, lane = tid & 31;
    const int c8 = tid & 7, rw = tid >> 3;

    auto resolve = [&](int t, TCfg& f) {
        GOp op; int lt;
        if (t < cum0)      { op = o0; lt = t; }
        else if (t < cum1) { op = o1; lt = t - cum0; }
        else               { op = o2; lt = t - cum1; }
        const int gx = op.Nt >> 7;
        f.n0 = (lt % gx) * 128;
        f.m0 = (lt / gx) * 128;
        if (CONV) f.rowbase = (f.m0 >> 8) * SP + (f.m0 & 255) + op.tapbase;
        else      f.rowbase = f.m0;
        f.Bh = op.Bh; f.ldB = op.ldB; f.Ktap = op.Ktap;
        f.kcpt = op.Ktap >> 6; f.nch = op.ntaps * f.kcpt;
        f.bias = op.bias; f.scl = op.scl;
        f.Ch = op.Ch; f.Cf = op.Cf; f.R = op.R; f.Nt = op.Nt;
    };

    auto load_chunk = [&](const TCfg& f, int c, int stage) {
        const int tap = c / f.kcpt;
        const int kt  = (c - tap * f.kcpt) << 6;
        const size_t aoff = (size_t)(f.rowbase + tap) * ldA + kt + c8 * 8;
        const size_t boff = (size_t)f.n0 * f.ldB + (size_t)tap * f.Ktap + kt + c8 * 8;
        const uint32_t st = sbase + stage * GSTAGE;
#pragma unroll
        for (int i = 0; i < 4; i++) {
            const int row = rw + i * 32;
            const uint32_t so = sw128r(row, c8);
            CP_ASYNC16(st +         so, Ah + aoff + (size_t)row * ldA);
            CP_ASYNC16(st + 16384 + so, f.Bh + boff + (size_t)row * f.ldB);
        }
        CP_ASYNC_COMMIT();
    };

    const int wm  = wid & 1,  wn  = wid >> 1;
    const int m0w = wm * 64,  n0w = wn * 32;
    const int tq  = lane >> 3, rin = lane & 7;
    const int aRow = m0w + (tq & 1) * 8 + rin;
    const int akh  = tq >> 1;
    const int bRow = n0w + (tq >> 1) * 8 + rin;
    const int bkh  = tq & 1;
    const int erow = lane >> 2;
    const int ecol = (lane & 3) * 2;

    int sg = 0;
    TCfg f;
    resolve(blockIdx.x, f);
    load_chunk(f, 0, 0);
    load_chunk(f, 1, 1);

    for (int t = blockIdx.x; t < ntot; t += gridDim.x) {
        float acc[4][4][4];
#pragma unroll
        for (int i = 0; i < 4; i++)
#pragma unroll
            for (int j = 0; j < 4; j++)
#pragma unroll
                for (int r = 0; r < 4; r++) acc[i][j][r] = 0.f;

        const int nch = f.nch;
        for (int c = 0; c < nch; c++) {
            if (c + 1 < nch) asm volatile("cp.async.wait_group 1;" ::: "memory");
            else             asm volatile("cp.async.wait_group 0;" ::: "memory");
            __syncthreads();
            if (c + 2 < nch) load_chunk(f, c + 2, (sg + c + 2) % 3);

            const uint32_t Ab = sbase + ((sg + c) % 3) * GSTAGE;
            const uint32_t Bb = Ab + 16384;

#pragma unroll
            for (int ks = 0; ks < 4; ks++) {
                uint32_t ah[4][4], bh[4][2];
#pragma unroll
                for (int mt = 0; mt < 4; mt++) {
                    const int r = aRow + mt * 16;   // r & 7 == rin
                    const uint32_t ad = Ab + (uint32_t)(r * 128)
                                      + (uint32_t)((((ks * 2 + akh) ^ rin) & 7) << 4);
                    ldsm4(ad, ah[mt][0], ah[mt][1], ah[mt][2], ah[mt][3]);
                }
#pragma unroll
                for (int nt2 = 0; nt2 < 2; nt2++) {
                    const int r = bRow + nt2 * 16;  // r & 7 == rin
                    const uint32_t bd = Bb + (uint32_t)(r * 128)
                                      + (uint32_t)((((ks * 2 + bkh) ^ rin) & 7) << 4);
                    uint32_t r0, r1, r2, r3;
                    ldsm4(bd, r0, r1, r2, r3);
                    bh[nt2 * 2][0] = r0; bh[nt2 * 2][1] = r1;
                    bh[nt2 * 2 + 1][0] = r2; bh[nt2 * 2 + 1][1] = r3;
                }
#pragma unroll
                for (int mt = 0; mt < 4; mt++)
#pragma unroll
                    for (int nt = 0; nt < 4; nt++)
                        mma_bf16(acc[mt][nt], ah[mt], bh[nt]);
            }
        }
        __syncthreads();   // all warps done reading smem before slot reuse
        sg += nch;

        // ---- cross-tile prefetch: next tile's first 2 chunks ----
        const int tn = t + gridDim.x;
        TCfg fn;
        if (tn < ntot) {
            resolve(tn, fn);
            load_chunk(fn, 0, sg % 3);
            load_chunk(fn, 1, (sg + 1) % 3);
        }

        // ---- epilogue (overlaps the prefetch) ----
#pragma unroll
        for (int mt = 0; mt < 4; mt++) {
#pragma unroll
            for (int nt = 0; nt < 4; nt++) {
                const int col = f.n0 + n0w + nt * 8 + ecol;
                const float2 bi = *(const float2*)&f.bias[col];
#pragma unroll
                for (int half = 0; half < 2; half++) {
                    const int row = f.m0 + m0w + mt * 16 + erow + half * 8;
                    float v0 = (acc[mt][nt][half * 2 + 0] + bi.x) * f.scl;
                    float v1 = (acc[mt][nt][half * 2 + 1] + bi.y) * f.scl;
                    if (EPI == 1) {
                        const float2 rr = *(const float2*)&f.R[(size_t)row * f.Nt + col];
                        v0 += rr.x; v1 += rr.y;
                        float2 o; o.x = v0; o.y = v1;
                        *(float2*)&f.Cf[(size_t)row * f.Nt + col] = o;
                    } else {
                        if (EPI == 2) {
                            v0 = v0 > 0.f ? v0 : 0.01f * v0;
                            v1 = v1 > 0.f ? v1 : 0.01f * v1;
                        }
                        *(uint32_t*)&f.Ch[(size_t)row * f.Nt + col] =
                            pack2(__float2bfloat16(v0), __float2bfloat16(v1));
                    }
                }
            }
        }
        if (tn < ntot) f = fn;
    }
}

// ---------------------------------------------------------------------------
// pad + convert x into bf16 padded buffer [bn][258][256]
// ---------------------------------------------------------------------------
__global__ __launch_bounds__(256)
void padcvt_x(const float* __restrict__ x, bf16* __restrict__ xh)
{
    const size_t i = (size_t)blockIdx.x * 256 + threadIdx.x;
    const int d = (int)(i & 255);
    const size_t rest = i >> 8;
    const int t = (int)(rest % SP);
    const size_t bn = rest / SP;
    float v = 0.f;
    if (t >= 1 && t <= S2) v = x[(bn * S2 + (t - 1)) * D + d];
    xh[i] = __float2bfloat16(v);
}

// ---------------------------------------------------------------------------
// fused weight transpose+convert (hi only): 6 weights in one launch
// ---------------------------------------------------------------------------
__global__ __launch_bounds__(256)
void wtall(const float* __restrict__ Wq, const float* __restrict__ Wk,
           const float* __restrict__ Wv, const float* __restrict__ Wo,
           const float* __restrict__ W1, const float* __restrict__ W2,
           bf16* wqh, bf16* wkh, bf16* wvh, bf16* woh, bf16* w1h, bf16* w2h)
{
    __shared__ float ts[32][33];
    const int t = blockIdx.x;
    const float* W; bf16* Bh; int K, N, lt;
    if      (t < 192) { W = Wq; Bh = wqh; K = 768;  N = 256;  lt = t; }
    else if (t < 384) { W = Wk; Bh = wkh; K = 768;  N = 256;  lt = t - 192; }
    else if (t < 448) { W = Wv; Bh = wvh; K = 256;  N = 256;  lt = t - 384; }
    else if (t < 512) { W = Wo; Bh = woh; K = 256;  N = 256;  lt = t - 448; }
    else if (t < 768) { W = W1; Bh = w1h; K = 256;  N = 1024; lt = t - 512; }
    else              { W = W2; Bh = w2h; K = 1024; N = 256;  lt = t - 768; }
    const int ntn = N / 32;
    const int n0 = (lt % ntn) * 32, k0 = (lt / ntn) * 32;
    const int tx = threadIdx.x, ty = threadIdx.y;   // 32 x 8
#pragma unroll
    for (int j = 0; j < 4; j++)
        ts[ty + j * 8][tx] = W[(size_t)(k0 + ty + j * 8) * N + n0 + tx];
    __syncthreads();
#pragma unroll
    for (int j = 0; j < 4; j++)
        Bh[(size_t)(n0 + ty + j * 8) * K + k0 + tx] = __float2bfloat16(ts[tx][ty + j * 8]);
}

// ---------------------------------------------------------------------------
// Flash attention on tensor cores, single-pass bf16, base-2 softmax
// (q pre-scaled by log2(e)/sqrt(HD); exp -> single ex2.approx).
// One block per (b,n,h); 8 warps x 32 rows. V B-frags via ldmatrix.x4.trans.
// smem: Qh Kh Vh, 3 x 20480 (rows stride 80B -> conflict-free)
// ---------------------------------------------------------------------------
constexpr int ATT_SMEM = 3 * 20480;   // 61440

__global__ __launch_bounds__(256, 2)
void attn_tc(const bf16* __restrict__ qh, const bf16* __restrict__ kh,
             const bf16* __restrict__ vh, bf16* __restrict__ oh)
{
    extern __shared__ char smem[];
    const uint32_t sb = smem_to_u32(smem);
    const uint32_t Qh = sb, Kh = sb + 20480, Vh = sb + 40960;

    const int tid = threadIdx.x, wid = tid >> 5, lane = tid & 31;
    const int h = blockIdx.x & 7, bn = blockIdx.x >> 3;
    const size_t gbase = (size_t)bn * 256 * 256 + h * 32;

    for (int idx = tid; idx < 1024; idx += 256) {
        const int row = idx >> 2, c = idx & 3;
        const size_t g = gbase + (size_t)row * 256 + c * 8;
        const uint32_t so = row * 80 + c * 16;
        CP_ASYNC16(Qh + so, qh + g);
        CP_ASYNC16(Kh + so, kh + g);
        CP_ASYNC16(Vh + so, vh + g);
    }
    CP_ASYNC_COMMIT();
    asm volatile("cp.async.wait_group 0;" ::: "memory");
    __syncthreads();

    const int tq = lane >> 3, rin = lane & 7;
    const int aR  = (tq & 1) * 8 + rin;
    const int akh = tq >> 1;
    const int bR  = (tq >> 1) * 8 + rin;
    const int bkh = tq & 1;
    const int vrow  = (lane & 7) + ((lane >> 3) & 1) * 8;
    const int vcolb = ((lane >> 4) & 1) * 16;

    uint32_t qf[2][2][4];
#pragma unroll
    for (int mt = 0; mt < 2; mt++)
#pragma unroll
        for (int ks = 0; ks < 2; ks++) {
            const uint32_t ad = Qh + (uint32_t)((wid * 32 + mt * 16 + aR) * 80)
                              + (uint32_t)((ks * 2 + akh) * 16);
            ldsm4(ad, qf[mt][ks][0], qf[mt][ks][1], qf[mt][ks][2], qf[mt][ks][3]);
        }

    float O[2][4][4];
#pragma unroll
    for (int mt = 0; mt < 2; mt++)
#pragma unroll
        for (int j = 0; j < 4; j++)
#pragma unroll
            for (int r = 0; r < 4; r++) O[mt][j][r] = 0.f;
    float mrow[2][2] = { {-1e30f, -1e30f}, {-1e30f, -1e30f} };
    float lrow[2][2] = { {0.f, 0.f}, {0.f, 0.f} };

    for (int s0 = 0; s0 < 256; s0 += 64) {
        float acc[2][8][4];
#pragma unroll
        for (int mt = 0; mt < 2; mt++)
#pragma unroll
            for (int j = 0; j < 8; j++)
#pragma unroll
                for (int r = 0; r < 4; r++) acc[mt][j][r] = 0.f;

#pragma unroll
        for (int ks = 0; ks < 2; ks++) {
            uint32_t kb[8][2];
#pragma unroll
            for (int g = 0; g < 4; g++) {
                const uint32_t kd = Kh + (uint32_t)((s0 + g * 16 + bR) * 80)
                                  + (uint32_t)((ks * 2 + bkh) * 16);
                uint32_t r0, r1, r2, r3;
                ldsm4(kd, r0, r1, r2, r3);
                kb[g * 2][0] = r0; kb[g * 2][1] = r1;
                kb[g * 2 + 1][0] = r2; kb[g * 2 + 1][1] = r3;
            }
#pragma unroll
            for (int mt = 0; mt < 2; mt++)
#pragma unroll
                for (int j = 0; j < 8; j++)
                    mma_bf16(acc[mt][j], qf[mt][ks], kb[j]);
        }

#pragma unroll
        for (int mt = 0; mt < 2; mt++) {
            float mxA = -1e30f, mxB = -1e30f;
#pragma unroll
            for (int j = 0; j < 8; j++) {
                mxA = fmaxf(mxA, fmaxf(acc[mt][j][0], acc[mt][j][1]));
                mxB = fmaxf(mxB, fmaxf(acc[mt][j][2], acc[mt][j][3]));
            }
            mxA = fmaxf(mxA, __shfl_xor_sync(0xffffffffu, mxA, 1));
            mxA = fmaxf(mxA, __shfl_xor_sync(0xffffffffu, mxA, 2));
            mxB = fmaxf(mxB, __shfl_xor_sync(0xffffffffu, mxB, 1));
            mxB = fmaxf(mxB, __shfl_xor_sync(0xffffffffu, mxB, 2));
            const float mnA = fmaxf(mrow[mt][0], mxA);
            const float mnB = fmaxf(mrow[mt][1], mxB);
            const float fA = ex2(mrow[mt][0] - mnA);
            const float fB = ex2(mrow[mt][1] - mnB);
            mrow[mt][0] = mnA; mrow[mt][1] = mnB;
            float sA = 0.f, sB = 0.f;
#pragma unroll
            for (int j = 0; j < 8; j++) {
                acc[mt][j][0] = ex2(acc[mt][j][0] - mnA);
                acc[mt][j][1] = ex2(acc[mt][j][1] - mnA);
                acc[mt][j][2] = ex2(acc[mt][j][2] - mnB);
                acc[mt][j][3] = ex2(acc[mt][j][3] - mnB);
                sA += acc[mt][j][0] + acc[mt][j][1];
                sB += acc[mt][j][2] + acc[mt][j][3];
            }
            lrow[mt][0] = lrow[mt][0] * fA + sA;
            lrow[mt][1] = lrow[mt][1] * fB + sB;
#pragma unroll
            for (int j = 0; j < 4; j++) {
                O[mt][j][0] *= fA; O[mt][j][1] *= fA;
                O[mt][j][2] *= fB; O[mt][j][3] *= fB;
            }
        }

#pragma unroll
        for (int kt = 0; kt < 4; kt++) {
            uint32_t vb[4][2];
#pragma unroll
            for (int nb = 0; nb < 2; nb++) {
                const uint32_t vd = Vh + (uint32_t)((s0 + kt * 16 + vrow) * 80)
                                  + (uint32_t)(nb * 32 + vcolb);
                uint32_t r0, r1, r2, r3;
                ldsm4t(vd, r0, r1, r2, r3);
                vb[nb * 2][0] = r0; vb[nb * 2][1] = r1;
                vb[nb * 2 + 1][0] = r2; vb[nb * 2 + 1][1] = r3;
            }
#pragma unroll
            for (int mt = 0; mt < 2; mt++) {
                uint32_t ph[4];
#pragma unroll
                for (int half = 0; half < 2; half++) {
                    const int j = 2 * kt + half;
                    ph[half * 2 + 0] = pack2(__float2bfloat16(acc[mt][j][0]),
                                             __float2bfloat16(acc[mt][j][1]));
                    ph[half * 2 + 1] = pack2(__float2bfloat16(acc[mt][j][2]),
                                             __float2bfloat16(acc[mt][j][3]));
                }
#pragma unroll
                for (int j2 = 0; j2 < 4; j2++)
                    mma_bf16(O[mt][j2], ph, vb[j2]);
            }
        }
    }

#pragma unroll
    for (int mt = 0; mt < 2; mt++) {
        float lA = lrow[mt][0], lB = lrow[mt][1];
        lA += __shfl_xor_sync(0xffffffffu, lA, 1);
        lA += __shfl_xor_sync(0xffffffffu, lA, 2);
        lB += __shfl_xor_sync(0xffffffffu, lB, 1);
        lB += __shfl_xor_sync(0xffffffffu, lB, 2);
        const float invA = 1.f / lA, invB = 1.f / lB;
        const int rowA = wid * 32 + mt * 16 + (lane >> 2);
        const size_t gA = gbase + (size_t)rowA * 256;
        const size_t gB = gA + (size_t)8 * 256;
#pragma unroll
        for (int j2 = 0; j2 < 4; j2++) {
            const int col = j2 * 8 + (lane & 3) * 2;
            *(uint32_t*)&oh[gA + col] = pack2(__float2bfloat16(O[mt][j2][0] * invA),
                                              __float2bfloat16(O[mt][j2][1] * invA));
            *(uint32_t*)&oh[gB + col] = pack2(__float2bfloat16(O[mt][j2][2] * invB),
                                              __float2bfloat16(O[mt][j2][3] * invB));
        }
    }
}

// ---------------------------------------------------------------------------
// LayerNorm (D=256). Optionally emits bf16 hi of the normalized output.
// ---------------------------------------------------------------------------
template<bool EMIT>
__global__ __launch_bounds__(256)
void ln_k(const float* __restrict__ X, const float* __restrict__ g,
          const float* __restrict__ be, float* __restrict__ Y,
          bf16* __restrict__ Yh)
{
    const int r    = blockIdx.x * 8 + (threadIdx.x >> 5);
    const int lane = threadIdx.x & 31;
    const float* xr = X + (long long)r * D;

    float xv[8];
    float s = 0.f, ss = 0.f;
#pragma unroll
    for (int j = 0; j < 8; j++) {
        const float t = xr[lane + j * 32];
        xv[j] = t; s += t; ss += t * t;
    }
#pragma unroll
    for (int ofs = 16; ofs > 0; ofs >>= 1) {
        s  += __shfl_xor_sync(0xffffffffu, s,  ofs);
        ss += __shfl_xor_sync(0xffffffffu, ss, ofs);
    }
    const float mu  = s * (1.f / 256.f);
    const float var = ss * (1.f / 256.f) - mu * mu;
    const float rs  = rsqrtf(var + 1e-5f);

#pragma unroll
    for (int j = 0; j < 8; j++) {
        const int d = lane + j * 32;
        const float y = (xv[j] - mu) * rs * g[d] + be[d];
        Y[(long long)r * D + d] = y;
        if (EMIT) Yh[(long long)r * D + d] = __float2bfloat16(y);
    }
}

// ---------------------------------------------------------------------------
extern "C" void kernel_launch(void* const* d_in, const int* in_sizes, int n_in,
                              void* d_out, int out_size)
{
    const float* x   = (const float*)d_in[0];
    const float* Wq  = (const float*)d_in[1];
    const float* bq  = (const float*)d_in[2];
    const float* Wk  = (const float*)d_in[3];
    const float* bk  = (const float*)d_in[4];
    const float* Wv  = (const float*)d_in[5];
    const float* bv  = (const float*)d_in[6];
    const float* Wo  = (const float*)d_in[7];
    const float* bo  = (const float*)d_in[8];
    const float* W1  = (const float*)d_in[9];
    const float* b1  = (const float*)d_in[10];
    const float* W2  = (const float*)d_in[11];
    const float* b2  = (const float*)d_in[12];
    const float* g1  = (const float*)d_in[13];
    const float* be1 = (const float*)d_in[14];
    const float* g2  = (const float*)d_in[15];
    const float* be2 = (const float*)d_in[16];
    float* out = (float*)d_out;

    bf16 *xph, *qh, *kh, *vh, *aoh, *hh, *ffh;
    bf16 *wqh, *wkh, *wvh, *woh, *w1h, *w2h;
    float *sb, *hbuf;
    cudaGetSymbolAddress((void**)&xph, g_xph);
    cudaGetSymbolAddress((void**)&qh,  g_qh);  cudaGetSymbolAddress((void**)&kh,  g_kh);
    cudaGetSymbolAddress((void**)&vh,  g_vh);  cudaGetSymbolAddress((void**)&aoh, g_aoh);
    cudaGetSymbolAddress((void**)&sb,  g_s);   cudaGetSymbolAddress((void**)&hbuf, g_h);
    cudaGetSymbolAddress((void**)&hh,  g_hh);  cudaGetSymbolAddress((void**)&ffh, g_ffh);
    cudaGetSymbolAddress((void**)&wqh, g_wqh); cudaGetSymbolAddress((void**)&wkh, g_wkh);
    cudaGetSymbolAddress((void**)&wvh, g_wvh); cudaGetSymbolAddress((void**)&woh, g_woh);
    cudaGetSymbolAddress((void**)&w1h, g_w1h); cudaGetSymbolAddress((void**)&w2h, g_w2h);

    cudaFuncSetAttribute(gemm_tc<4, true>,  cudaFuncAttributeMaxDynamicSharedMemorySize, GSMEM);
    cudaFuncSetAttribute(gemm_tc<1, false>, cudaFuncAttributeMaxDynamicSharedMemorySize, GSMEM);
    cudaFuncSetAttribute(gemm_tc<2, false>, cudaFuncAttributeMaxDynamicSharedMemorySize, GSMEM);
    cudaFuncSetAttribute(attn_tc, cudaFuncAttributeMaxDynamicSharedMemorySize, ATT_SMEM);

    int smCount = 148;
    cudaDeviceGetAttribute(&smCount, cudaDevAttrMultiProcessorCount, 0);
    const int G = smCount * 2;

    padcvt_x<<<(BN_ * SP * D) / 256, 256>>>(x, xph);
    wtall<<<1024, dim3(32, 8)>>>(Wq, Wk, Wv, Wo, W1, W2, wqh, wkh, wvh, woh, w1h, w2h);

    // q pre-scaled by log2(e)/sqrt(32) for base-2 softmax
    const float qscale = 0.2550663527668625f;
    GOp dummy = {};

    // ---- fused QKV (persistent, 3 ops, 3072 tiles) ----
    {
        GOp oq = { wqh, bq, qscale, qh, nullptr, nullptr, 3 * D, D, 3, 0, D };
        GOp ok = { wkh, bk, 1.f,    kh, nullptr, nullptr, 3 * D, D, 3, 0, D };
        GOp ov = { wvh, bv, 1.f,    vh, nullptr, nullptr, D,     D, 1, 1, D };
        gemm_tc<4, true><<<G, 256, GSMEM>>>(xph, D, oq, ok, ov, 1024, 2048, 3072);
    }
    attn_tc<<<Bd * S1 * Hh, 256, ATT_SMEM>>>(qh, kh, vh, aoh);
    {   // s = x + ao@Wo + bo
        GOp oo = { woh, bo, 1.f, nullptr, sb, x, D, D, 1, 0, D };
        gemm_tc<1, false><<<G, 256, GSMEM>>>(aoh, D, oo, dummy, dummy, 1024, 1024, 1024);
    }
    ln_k<true><<<TOK / 8, 256>>>(sb, g1, be1, hbuf, hh);
    {   // ff = leaky(h@W1 + b1)
        GOp o1 = { w1h, b1, 1.f, ffh, nullptr, nullptr, D, D, 1, 0, Fd };
        gemm_tc<2, false><<<G, 256, GSMEM>>>(hh, D, o1, dummy, dummy, 4096, 4096, 4096);
    }
    {   // s = h + ff@W2 + b2
        GOp o2 = { w2h, b2, 1.f, nullptr, sb, hbuf, Fd, Fd, 1, 0, D };
        gemm_tc<1, false><<<G, 256, GSMEM>>>(ffh, Fd, o2, dummy, dummy, 1024, 1024, 1024);
    }
    ln_k<false><<<TOK / 8, 256>>>(sb, g2, be2, out, nullptr);
}

// round 15
// speedup vs baseline: 1.1158x; 1.1158x over previous
#include <cuda_runtime.h>
#include <cuda_bf16.h>
#include <cstdint>
#include <math.h>

using bf16 = __nv_bfloat16;

// ---------------- problem constants ----------------
constexpr int Bd  = 4;
constexpr int S1  = 64;
constexpr int S2  = 256;
constexpr int D   = 256;
constexpr int Hh  = 8;
constexpr int HD  = 32;
constexpr int Fd  = 1024;
constexpr int TOK = Bd * S1 * S2;     // 65536
constexpr int BN_ = Bd * S1;          // 256
constexpr int SP  = S2 + 2;           // padded time length 258

// ---------------- scratch (device globals) ----------------
__device__ bf16  g_xph[BN_ * SP * D];
__device__ bf16  g_qh [TOK * D];
__device__ bf16  g_kh [TOK * D];
__device__ bf16  g_vh [TOK * D];
__device__ bf16  g_aoh[TOK * D];
__device__ float g_s  [TOK * D];
__device__ float g_h  [TOK * D];
__device__ bf16  g_hh [TOK * D];
__device__ bf16  g_ffh[TOK * Fd];
// transposed weights (hi only)
__device__ bf16 g_wqh[D * 3 * D];
__device__ bf16 g_wkh[D * 3 * D];
__device__ bf16 g_wvh[D * D];
__device__ bf16 g_woh[D * D];
__device__ bf16 g_w1h[Fd * D];
__device__ bf16 g_w2h[D * Fd];

// ---------------- helpers ----------------
__device__ __forceinline__ uint32_t smem_to_u32(const void* p) {
    uint32_t a;
    asm("{ .reg .u64 t; cvta.to.shared.u64 t, %1; cvt.u32.u64 %0, t; }" : "=r"(a) : "l"(p));
    return a;
}
#define CP_ASYNC16(s, g) \
    asm volatile("cp.async.cg.shared.global [%0], [%1], 16;" :: "r"((uint32_t)(s)), "l"(g))
#define CP_ASYNC_COMMIT() asm volatile("cp.async.commit_group;" ::: "memory")

__device__ __forceinline__ void ldsm4(uint32_t addr, uint32_t& r0, uint32_t& r1,
                                      uint32_t& r2, uint32_t& r3) {
    asm volatile("ldmatrix.sync.aligned.m8n8.x4.shared.b16 {%0,%1,%2,%3}, [%4];"
                 : "=r"(r0), "=r"(r1), "=r"(r2), "=r"(r3) : "r"(addr));
}
__device__ __forceinline__ void ldsm4t(uint32_t addr, uint32_t& r0, uint32_t& r1,
                                       uint32_t& r2, uint32_t& r3) {
    asm volatile("ldmatrix.sync.aligned.m8n8.x4.trans.shared.b16 {%0,%1,%2,%3}, [%4];"
                 : "=r"(r0), "=r"(r1), "=r"(r2), "=r"(r3) : "r"(addr));
}
__device__ __forceinline__ void mma_bf16(float* c, const uint32_t* a, const uint32_t* b) {
    asm volatile("mma.sync.aligned.m16n8k16.row.col.f32.bf16.bf16.f32 "
                 "{%0,%1,%2,%3}, {%4,%5,%6,%7}, {%8,%9}, {%0,%1,%2,%3};"
                 : "+f"(c[0]), "+f"(c[1]), "+f"(c[2]), "+f"(c[3])
                 : "r"(a[0]), "r"(a[1]), "r"(a[2]), "r"(a[3]), "r"(b[0]), "r"(b[1]));
}
__device__ __forceinline__ float ex2(float x) {
    float y; asm("ex2.approx.f32 %0, %1;" : "=f"(y) : "f"(x)); return y;
}
__device__ __forceinline__ uint32_t pack2(bf16 a, bf16 b) {
    __nv_bfloat162 p; p.x = a; p.y = b;
    return *(uint32_t*)&p;
}
// 128B-row swizzle (BK=64): 8 16B cols, XOR by row&7 (SW128)
__device__ __forceinline__ uint32_t sw128r(int row, int c) {
    return (uint32_t)(row * 128 + ((c ^ (row & 7)) << 4));
}

// ---------------------------------------------------------------------------
// Tensor-core GEMM via mma.sync bf16, 128x128 block tile, BK=64, 1-pass,
// 3-stage cp.async pipeline, 2 CTAs/SM. gridDim.z == 2 -> blockIdx.z picks
// second weight/bias/output set (used to fuse Q and K).
// stage (32KB): [Ah 16K][Bh 16K] (128B rows, sw128r)
// EPI: 1 = bias*scl + R -> fp32 ; 2 = bias*scl + leaky -> bf16 hi ;
//      4 = bias*scl -> bf16 hi
// ---------------------------------------------------------------------------
constexpr int GSTAGE = 32768;
constexpr int GSMEM  = 3 * GSTAGE;   // 98304

template<int EPI, bool CONV>
__global__ __launch_bounds__(256, 2)
void gemm_tc(const bf16* __restrict__ Ah, int ldA,
             const bf16* Bh_, int ldB,
             int Ktap, int ntaps, int tapbase, float scl_,
             const float* bias_, const float* __restrict__ R,
             float* __restrict__ Cf, bf16* Ch_, int Nt,
             const bf16* Bh2, const float* bias2, float scl2, bf16* Ch2)
{
    extern __shared__ char smem[];
    const uint32_t sbase = smem_to_u32(smem);
    const int tid = threadIdx.x, wid = tid >> 5, lane = tid & 31;
    const int m0 = blockIdx.y * 128, n0 = blockIdx.x * 128;

    const bf16* Bh = Bh_;
    const float* bias = bias_;  float scl = scl_;
    bf16* Ch = Ch_;
    if (blockIdx.z == 1) { Bh = Bh2; bias = bias2; scl = scl2; Ch = Ch2; }

    int rowbase;
    if (CONV) { const int bn = m0 >> 8; const int t0 = m0 & 255; rowbase = bn * SP + t0 + tapbase; }
    else      { rowbase = m0; }

    const int kcpt = Ktap >> 6;          // 64-wide chunks per tap
    const int nch  = ntaps * kcpt;
    const int c8   = tid & 7;            // 16B col 0..7
    const int rw   = tid >> 3;           // row 0..31

    auto load_chunk = [&](int c, int stage) {
        const int tap = c / kcpt;
        const int kt  = (c - tap * kcpt) << 6;
        const size_t aoff = (size_t)(rowbase + tap) * ldA + kt + c8 * 8;
        const size_t boff = (size_t)n0 * ldB + (size_t)tap * Ktap + kt + c8 * 8;
        const uint32_t st = sbase + stage * GSTAGE;
#pragma unroll
        for (int i = 0; i < 4; i++) {
            const int row = rw + i * 32;
            const uint32_t so = sw128r(row, c8);
            CP_ASYNC16(st +         so, Ah + aoff + (size_t)row * ldA);
            CP_ASYNC16(st + 16384 + so, Bh + boff + (size_t)row * ldB);
        }
        CP_ASYNC_COMMIT();
    };

    load_chunk(0, 0);
    load_chunk(1, 1);

    const int wm  = wid & 1,  wn  = wid >> 1;
    const int m0w = wm * 64,  n0w = wn * 32;
    const int tq  = lane >> 3, rin = lane & 7;
    const int aRow = m0w + (tq & 1) * 8 + rin;
    const int akh  = tq >> 1;
    const int bRow = n0w + (tq >> 1) * 8 + rin;
    const int bkh  = tq & 1;

    float acc[4][4][4];
#pragma unroll
    for (int i = 0; i < 4; i++)
#pragma unroll
        for (int j = 0; j < 4; j++)
#pragma unroll
            for (int r = 0; r < 4; r++) acc[i][j][r] = 0.f;

    for (int c = 0; c < nch; c++) {
        if (c + 1 < nch) asm volatile("cp.async.wait_group 1;" ::: "memory");
        else             asm volatile("cp.async.wait_group 0;" ::: "memory");
        __syncthreads();
        if (c + 2 < nch) load_chunk(c + 2, (c + 2) % 3);

        const uint32_t Ab = sbase + (c % 3) * GSTAGE;
        const uint32_t Bb = Ab + 16384;

#pragma unroll
        for (int ks = 0; ks < 4; ks++) {
            uint32_t ah[4][4], bh[4][2];
#pragma unroll
            for (int mt = 0; mt < 4; mt++) {
                const int r = aRow + mt * 16;   // r & 7 == rin
                const uint32_t ad = Ab + (uint32_t)(r * 128)
                                  + (uint32_t)((((ks * 2 + akh) ^ rin) & 7) << 4);
                ldsm4(ad, ah[mt][0], ah[mt][1], ah[mt][2], ah[mt][3]);
            }
#pragma unroll
            for (int nt2 = 0; nt2 < 2; nt2++) {
                const int r = bRow + nt2 * 16;  // r & 7 == rin
                const uint32_t bd = Bb + (uint32_t)(r * 128)
                                  + (uint32_t)((((ks * 2 + bkh) ^ rin) & 7) << 4);
                uint32_t r0, r1, r2, r3;
                ldsm4(bd, r0, r1, r2, r3);
                bh[nt2 * 2][0] = r0; bh[nt2 * 2][1] = r1;
                bh[nt2 * 2 + 1][0] = r2; bh[nt2 * 2 + 1][1] = r3;
            }
#pragma unroll
            for (int mt = 0; mt < 4; mt++)
#pragma unroll
                for (int nt = 0; nt < 4; nt++)
                    mma_bf16(acc[mt][nt], ah[mt], bh[nt]);
        }
    }

    const int erow = lane >> 2;
    const int ecol = (lane & 3) * 2;
#pragma unroll
    for (int mt = 0; mt < 4; mt++) {
#pragma unroll
        for (int nt = 0; nt < 4; nt++) {
            const int col = n0 + n0w + nt * 8 + ecol;
            const float2 bi = *(const float2*)&bias[col];
#pragma unroll
            for (int half = 0; half < 2; half++) {
                const int row = m0 + m0w + mt * 16 + erow + half * 8;
                float v0 = (acc[mt][nt][half * 2 + 0] + bi.x) * scl;
                float v1 = (acc[mt][nt][half * 2 + 1] + bi.y) * scl;
                if (EPI == 1) {
                    const float2 rr = *(const float2*)&R[(size_t)row * Nt + col];
                    v0 += rr.x; v1 += rr.y;
                    float2 o; o.x = v0; o.y = v1;
                    *(float2*)&Cf[(size_t)row * Nt + col] = o;
                } else {
                    if (EPI == 2) {
                        v0 = v0 > 0.f ? v0 : 0.01f * v0;
                        v1 = v1 > 0.f ? v1 : 0.01f * v1;
                    }
                    *(uint32_t*)&Ch[(size_t)row * Nt + col] =
                        pack2(__float2bfloat16(v0), __float2bfloat16(v1));
                }
            }
        }
    }
}

// ---------------------------------------------------------------------------
// pad + convert x into bf16 padded buffer [bn][258][256]
// ---------------------------------------------------------------------------
__global__ __launch_bounds__(256)
void padcvt_x(const float* __restrict__ x, bf16* __restrict__ xh)
{
    const size_t i = (size_t)blockIdx.x * 256 + threadIdx.x;
    const int d = (int)(i & 255);
    const size_t rest = i >> 8;
    const int t = (int)(rest % SP);
    const size_t bn = rest / SP;
    float v = 0.f;
    if (t >= 1 && t <= S2) v = x[(bn * S2 + (t - 1)) * D + d];
    xh[i] = __float2bfloat16(v);
}

// ---------------------------------------------------------------------------
// fused weight transpose+convert (hi only): 6 weights in one launch
// ---------------------------------------------------------------------------
__global__ __launch_bounds__(256)
void wtall(const float* __restrict__ Wq, const float* __restrict__ Wk,
           const float* __restrict__ Wv, const float* __restrict__ Wo,
           const float* __restrict__ W1, const float* __restrict__ W2,
           bf16* wqh, bf16* wkh, bf16* wvh, bf16* woh, bf16* w1h, bf16* w2h)
{
    __shared__ float ts[32][33];
    const int t = blockIdx.x;
    const float* W; bf16* Bh; int K, N, lt;
    if      (t < 192) { W = Wq; Bh = wqh; K = 768;  N = 256;  lt = t; }
    else if (t < 384) { W = Wk; Bh = wkh; K = 768;  N = 256;  lt = t - 192; }
    else if (t < 448) { W = Wv; Bh = wvh; K = 256;  N = 256;  lt = t - 384; }
    else if (t < 512) { W = Wo; Bh = woh; K = 256;  N = 256;  lt = t - 448; }
    else if (t < 768) { W = W1; Bh = w1h; K = 256;  N = 1024; lt = t - 512; }
    else              { W = W2; Bh = w2h; K = 1024; N = 256;  lt = t - 768; }
    const int ntn = N / 32;
    const int n0 = (lt % ntn) * 32, k0 = (lt / ntn) * 32;
    const int tx = threadIdx.x, ty = threadIdx.y;   // 32 x 8
#pragma unroll
    for (int j = 0; j < 4; j++)
        ts[ty + j * 8][tx] = W[(size_t)(k0 + ty + j * 8) * N + n0 + tx];
    __syncthreads();
#pragma unroll
    for (int j = 0; j < 4; j++)
        Bh[(size_t)(n0 + ty + j * 8) * K + k0 + tx] = __float2bfloat16(ts[tx][ty + j * 8]);
}

// ---------------------------------------------------------------------------
// Flash attention on tensor cores, single-pass bf16, base-2 softmax
// (q pre-scaled by log2(e)/sqrt(HD); exp -> single ex2.approx).
// One block per (b,n,h); 8 warps x 32 rows. V B-frags via ldmatrix.x4.trans.
// smem: Qh Kh Vh, 3 x 20480 (rows stride 80B -> conflict-free)
// ---------------------------------------------------------------------------
constexpr int ATT_SMEM = 3 * 20480;   // 61440

__global__ __launch_bounds__(256, 2)
void attn_tc(const bf16* __restrict__ qh, const bf16* __restrict__ kh,
             const bf16* __restrict__ vh, bf16* __restrict__ oh)
{
    extern __shared__ char smem[];
    const uint32_t sb = smem_to_u32(smem);
    const uint32_t Qh = sb, Kh = sb + 20480, Vh = sb + 40960;

    const int tid = threadIdx.x, wid = tid >> 5, lane = tid & 31;
    const int h = blockIdx.x & 7, bn = blockIdx.x >> 3;
    const size_t gbase = (size_t)bn * 256 * 256 + h * 32;

    for (int idx = tid; idx < 1024; idx += 256) {
        const int row = idx >> 2, c = idx & 3;
        const size_t g = gbase + (size_t)row * 256 + c * 8;
        const uint32_t so = row * 80 + c * 16;
        CP_ASYNC16(Qh + so, qh + g);
        CP_ASYNC16(Kh + so, kh + g);
        CP_ASYNC16(Vh + so, vh + g);
    }
    CP_ASYNC_COMMIT();
    asm volatile("cp.async.wait_group 0;" ::: "memory");
    __syncthreads();

    const int tq = lane >> 3, rin = lane & 7;
    const int aR  = (tq & 1) * 8 + rin;
    const int akh = tq >> 1;
    const int bR  = (tq >> 1) * 8 + rin;
    const int bkh = tq & 1;
    const int vrow  = (lane & 7) + ((lane >> 3) & 1) * 8;
    const int vcolb = ((lane >> 4) & 1) * 16;

    uint32_t qf[2][2][4];
#pragma unroll
    for (int mt = 0; mt < 2; mt++)
#pragma unroll
        for (int ks = 0; ks < 2; ks++) {
            const uint32_t ad = Qh + (uint32_t)((wid * 32 + mt * 16 + aR) * 80)
                              + (uint32_t)((ks * 2 + akh) * 16);
            ldsm4(ad, qf[mt][ks][0], qf[mt][ks][1], qf[mt][ks][2], qf[mt][ks][3]);
        }

    float O[2][4][4];
#pragma unroll
    for (int mt = 0; mt < 2; mt++)
#pragma unroll
        for (int j = 0; j < 4; j++)
#pragma unroll
            for (int r = 0; r < 4; r++) O[mt][j][r] = 0.f;
    float mrow[2][2] = { {-1e30f, -1e30f}, {-1e30f, -1e30f} };
    float lrow[2][2] = { {0.f, 0.f}, {0.f, 0.f} };

    for (int s0 = 0; s0 < 256; s0 += 64) {
        float acc[2][8][4];
#pragma unroll
        for (int mt = 0; mt < 2; mt++)
#pragma unroll
            for (int j = 0; j < 8; j++)
#pragma unroll
                for (int r = 0; r < 4; r++) acc[mt][j][r] = 0.f;

#pragma unroll
        for (int ks = 0; ks < 2; ks++) {
            uint32_t kb[8][2];
#pragma unroll
            for (int g = 0; g < 4; g++) {
                const uint32_t kd = Kh + (uint32_t)((s0 + g * 16 + bR) * 80)
                                  + (uint32_t)((ks * 2 + bkh) * 16);
                uint32_t r0, r1, r2, r3;
                ldsm4(kd, r0, r1, r2, r3);
                kb[g * 2][0] = r0; kb[g * 2][1] = r1;
                kb[g * 2 + 1][0] = r2; kb[g * 2 + 1][1] = r3;
            }
#pragma unroll
            for (int mt = 0; mt < 2; mt++)
#pragma unroll
                for (int j = 0; j < 8; j++)
                    mma_bf16(acc[mt][j], qf[mt][ks], kb[j]);
        }

#pragma unroll
        for (int mt = 0; mt < 2; mt++) {
            float mxA = -1e30f, mxB = -1e30f;
#pragma unroll
            for (int j = 0; j < 8; j++) {
                mxA = fmaxf(mxA, fmaxf(acc[mt][j][0], acc[mt][j][1]));
                mxB = fmaxf(mxB, fmaxf(acc[mt][j][2], acc[mt][j][3]));
            }
            mxA = fmaxf(mxA, __shfl_xor_sync(0xffffffffu, mxA, 1));
            mxA = fmaxf(mxA, __shfl_xor_sync(0xffffffffu, mxA, 2));
            mxB = fmaxf(mxB, __shfl_xor_sync(0xffffffffu, mxB, 1));
            mxB = fmaxf(mxB, __shfl_xor_sync(0xffffffffu, mxB, 2));
            const float mnA = fmaxf(mrow[mt][0], mxA);
            const float mnB = fmaxf(mrow[mt][1], mxB);
            const float fA = ex2(mrow[mt][0] - mnA);
            const float fB = ex2(mrow[mt][1] - mnB);
            mrow[mt][0] = mnA; mrow[mt][1] = mnB;
            float sA = 0.f, sB = 0.f;
#pragma unroll
            for (int j = 0; j < 8; j++) {
                acc[mt][j][0] = ex2(acc[mt][j][0] - mnA);
                acc[mt][j][1] = ex2(acc[mt][j][1] - mnA);
                acc[mt][j][2] = ex2(acc[mt][j][2] - mnB);
                acc[mt][j][3] = ex2(acc[mt][j][3] - mnB);
                sA += acc[mt][j][0] + acc[mt][j][1];
                sB += acc[mt][j][2] + acc[mt][j][3];
            }
            lrow[mt][0] = lrow[mt][0] * fA + sA;
            lrow[mt][1] = lrow[mt][1] * fB + sB;
#pragma unroll
            for (int j = 0; j < 4; j++) {
                O[mt][j][0] *= fA; O[mt][j][1] *= fA;
                O[mt][j][2] *= fB; O[mt][j][3] *= fB;
            }
        }

#pragma unroll
        for (int kt = 0; kt < 4; kt++) {
            uint32_t vb[4][2];
#pragma unroll
            for (int nb = 0; nb < 2; nb++) {
                const uint32_t vd = Vh + (uint32_t)((s0 + kt * 16 + vrow) * 80)
                                  + (uint32_t)(nb * 32 + vcolb);
                uint32_t r0, r1, r2, r3;
                ldsm4t(vd, r0, r1, r2, r3);
                vb[nb * 2][0] = r0; vb[nb * 2][1] = r1;
                vb[nb * 2 + 1][0] = r2; vb[nb * 2 + 1][1] = r3;
            }
#pragma unroll
            for (int mt = 0; mt < 2; mt++) {
                uint32_t ph[4];
#pragma unroll
                for (int half = 0; half < 2; half++) {
                    const int j = 2 * kt + half;
                    ph[half * 2 + 0] = pack2(__float2bfloat16(acc[mt][j][0]),
                                             __float2bfloat16(acc[mt][j][1]));
                    ph[half * 2 + 1] = pack2(__float2bfloat16(acc[mt][j][2]),
                                             __float2bfloat16(acc[mt][j][3]));
                }
#pragma unroll
                for (int j2 = 0; j2 < 4; j2++)
                    mma_bf16(O[mt][j2], ph, vb[j2]);
            }
        }
    }

#pragma unroll
    for (int mt = 0; mt < 2; mt++) {
        float lA = lrow[mt][0], lB = lrow[mt][1];
        lA += __shfl_xor_sync(0xffffffffu, lA, 1);
        lA += __shfl_xor_sync(0xffffffffu, lA, 2);
        lB += __shfl_xor_sync(0xffffffffu, lB, 1);
        lB += __shfl_xor_sync(0xffffffffu, lB, 2);
        const float invA = 1.f / lA, invB = 1.f / lB;
        const int rowA = wid * 32 + mt * 16 + (lane >> 2);
        const size_t gA = gbase + (size_t)rowA * 256;
        const size_t gB = gA + (size_t)8 * 256;
#pragma unroll
        for (int j2 = 0; j2 < 4; j2++) {
            const int col = j2 * 8 + (lane & 3) * 2;
            *(uint32_t*)&oh[gA + col] = pack2(__float2bfloat16(O[mt][j2][0] * invA),
                                              __float2bfloat16(O[mt][j2][1] * invA));
            *(uint32_t*)&oh[gB + col] = pack2(__float2bfloat16(O[mt][j2][2] * invB),
                                              __float2bfloat16(O[mt][j2][3] * invB));
        }
    }
}

// ---------------------------------------------------------------------------
// LayerNorm (D=256). Optionally emits bf16 hi of the normalized output.
// ---------------------------------------------------------------------------
template<bool EMIT>
__global__ __launch_bounds__(256)
void ln_k(const float* __restrict__ X, const float* __restrict__ g,
          const float* __restrict__ be, float* __restrict__ Y,
          bf16* __restrict__ Yh)
{
    const int r    = blockIdx.x * 8 + (threadIdx.x >> 5);
    const int lane = threadIdx.x & 31;
    const float* xr = X + (long long)r * D;

    float xv[8];
    float s = 0.f, ss = 0.f;
#pragma unroll
    for (int j = 0; j < 8; j++) {
        const float t = xr[lane + j * 32];
        xv[j] = t; s += t; ss += t * t;
    }
#pragma unroll
    for (int ofs = 16; ofs > 0; ofs >>= 1) {
        s  += __shfl_xor_sync(0xffffffffu, s,  ofs);
        ss += __shfl_xor_sync(0xffffffffu, ss, ofs);
    }
    const float mu  = s * (1.f / 256.f);
    const float var = ss * (1.f / 256.f) - mu * mu;
    const float rs  = rsqrtf(var + 1e-5f);

#pragma unroll
    for (int j = 0; j < 8; j++) {
        const int d = lane + j * 32;
        const float y = (xv[j] - mu) * rs * g[d] + be[d];
        Y[(long long)r * D + d] = y;
        if (EMIT) Yh[(long long)r * D + d] = __float2bfloat16(y);
    }
}

// ---------------------------------------------------------------------------
extern "C" void kernel_launch(void* const* d_in, const int* in_sizes, int n_in,
                              void* d_out, int out_size)
{
    const float* x   = (const float*)d_in[0];
    const float* Wq  = (const float*)d_in[1];
    const float* bq  = (const float*)d_in[2];
    const float* Wk  = (const float*)d_in[3];
    const float* bk  = (const float*)d_in[4];
    const float* Wv  = (const float*)d_in[5];
    const float* bv  = (const float*)d_in[6];
    const float* Wo  = (const float*)d_in[7];
    const float* bo  = (const float*)d_in[8];
    const float* W1  = (const float*)d_in[9];
    const float* b1  = (const float*)d_in[10];
    const float* W2  = (const float*)d_in[11];
    const float* b2  = (const float*)d_in[12];
    const float* g1  = (const float*)d_in[13];
    const float* be1 = (const float*)d_in[14];
    const float* g2  = (const float*)d_in[15];
    const float* be2 = (const float*)d_in[16];
    float* out = (float*)d_out;

    bf16 *xph, *qh, *kh, *vh, *aoh, *hh, *ffh;
    bf16 *wqh, *wkh, *wvh, *woh, *w1h, *w2h;
    float *sb, *hbuf;
    cudaGetSymbolAddress((void**)&xph, g_xph);
    cudaGetSymbolAddress((void**)&qh,  g_qh);  cudaGetSymbolAddress((void**)&kh,  g_kh);
    cudaGetSymbolAddress((void**)&vh,  g_vh);  cudaGetSymbolAddress((void**)&aoh, g_aoh);
    cudaGetSymbolAddress((void**)&sb,  g_s);   cudaGetSymbolAddress((void**)&hbuf, g_h);
    cudaGetSymbolAddress((void**)&hh,  g_hh);  cudaGetSymbolAddress((void**)&ffh, g_ffh);
    cudaGetSymbolAddress((void**)&wqh, g_wqh); cudaGetSymbolAddress((void**)&wkh, g_wkh);
    cudaGetSymbolAddress((void**)&wvh, g_wvh); cudaGetSymbolAddress((void**)&woh, g_woh);
    cudaGetSymbolAddress((void**)&w1h, g_w1h); cudaGetSymbolAddress((void**)&w2h, g_w2h);

    cudaFuncSetAttribute(gemm_tc<4, true>,  cudaFuncAttributeMaxDynamicSharedMemorySize, GSMEM);
    cudaFuncSetAttribute(gemm_tc<1, false>, cudaFuncAttributeMaxDynamicSharedMemorySize, GSMEM);
    cudaFuncSetAttribute(gemm_tc<2, false>, cudaFuncAttributeMaxDynamicSharedMemorySize, GSMEM);
    cudaFuncSetAttribute(attn_tc, cudaFuncAttributeMaxDynamicSharedMemorySize, ATT_SMEM);

    padcvt_x<<<(BN_ * SP * D) / 256, 256>>>(x, xph);
    wtall<<<1024, dim3(32, 8)>>>(Wq, Wk, Wv, Wo, W1, W2, wqh, wkh, wvh, woh, w1h, w2h);

    const dim3 gQK(D / 128, TOK / 128, 2);
    const dim3 gD (D / 128, TOK / 128);
    const dim3 gF (Fd / 128, TOK / 128);
    // q pre-scaled by log2(e)/sqrt(32) for base-2 softmax (ex2)
    const float qscale = 0.2550663527668625f;

    // Q+K fused (3-tap conv, 1-pass, BK=64, hi out; Q pre-scaled; ldB = 3*D)
    gemm_tc<4, true><<<gQK, 256, GSMEM>>>(xph, D, wqh, 3 * D, D, 3, 0, qscale,
                                          bq, nullptr, nullptr, qh, D,
                                          wkh, bk, 1.f, kh);
    // V (1-pass, BK=64, hi out; center tap)
    gemm_tc<4, true><<<gD, 256, GSMEM>>>(xph, D, wvh, D, D, 1, 1, 1.f,
                                         bv, nullptr, nullptr, vh, D,
                                         nullptr, nullptr, 0.f, nullptr);
    // attention (single-pass bf16, base-2 softmax)
    attn_tc<<<Bd * S1 * Hh, 256, ATT_SMEM>>>(qh, kh, vh, aoh);
    // s = x + ao@Wo + bo
    gemm_tc<1, false><<<gD, 256, GSMEM>>>(aoh, D, woh, D, D, 1, 0, 1.f,
                                          bo, x, sb, nullptr, D,
                                          nullptr, nullptr, 0.f, nullptr);
    ln_k<true><<<TOK / 8, 256>>>(sb, g1, be1, hbuf, hh);
    // ff = leaky(h@W1 + b1)
    gemm_tc<2, false><<<gF, 256, GSMEM>>>(hh, D, w1h, D, D, 1, 0, 1.f,
                                          b1, nullptr, nullptr, ffh, Fd,
                                          nullptr, nullptr, 0.f, nullptr);
    // s = h + ff@W2 + b2
    gemm_tc<1, false><<<gD, 256, GSMEM>>>(ffh, Fd, w2h, Fd, Fd, 1, 0, 1.f,
                                          b2, hbuf, sb, nullptr, D,
                                          nullptr, nullptr, 0.f, nullptr);
    ln_k<false><<<TOK / 8, 256>>>(sb, g2, be2, out, nullptr);
}

// round 16
// speedup vs baseline: 1.1172x; 1.0012x over previous
#include <cuda_runtime.h>
#include <cuda_bf16.h>
#include <cstdint>
#include <math.h>

using bf16 = __nv_bfloat16;

// ---------------- problem constants ----------------
constexpr int Bd  = 4;
constexpr int S1  = 64;
constexpr int S2  = 256;
constexpr int D   = 256;
constexpr int Hh  = 8;
constexpr int HD  = 32;
constexpr int Fd  = 1024;
constexpr int TOK = Bd * S1 * S2;     // 65536
constexpr int BN_ = Bd * S1;          // 256
constexpr int SP  = S2 + 2;           // padded time length 258

// ---------------- scratch (device globals) ----------------
__device__ bf16  g_xph[BN_ * SP * D];
__device__ bf16  g_qh [TOK * D];
__device__ bf16  g_kh [TOK * D];
__device__ bf16  g_vh [TOK * D];
__device__ bf16  g_aoh[TOK * D];
__device__ float g_s  [TOK * D];
__device__ float g_h  [TOK * D];
__device__ bf16  g_hh [TOK * D];
__device__ bf16  g_ffh[TOK * Fd];
// transposed weights (hi only)
__device__ bf16 g_wqh[D * 3 * D];
__device__ bf16 g_wkh[D * 3 * D];
__device__ bf16 g_wvh[D * D];
__device__ bf16 g_woh[D * D];
__device__ bf16 g_w1h[Fd * D];
__device__ bf16 g_w2h[D * Fd];

// ---------------- helpers ----------------
__device__ __forceinline__ uint32_t smem_to_u32(const void* p) {
    uint32_t a;
    asm("{ .reg .u64 t; cvta.to.shared.u64 t, %1; cvt.u32.u64 %0, t; }" : "=r"(a) : "l"(p));
    return a;
}
#define CP_ASYNC16(s, g) \
    asm volatile("cp.async.cg.shared.global [%0], [%1], 16;" :: "r"((uint32_t)(s)), "l"(g))
#define CP_ASYNC_COMMIT() asm volatile("cp.async.commit_group;" ::: "memory")

__device__ __forceinline__ void ldsm4(uint32_t addr, uint32_t& r0, uint32_t& r1,
                                      uint32_t& r2, uint32_t& r3) {
    asm volatile("ldmatrix.sync.aligned.m8n8.x4.shared.b16 {%0,%1,%2,%3}, [%4];"
                 : "=r"(r0), "=r"(r1), "=r"(r2), "=r"(r3) : "r"(addr));
}
__device__ __forceinline__ void ldsm4t(uint32_t addr, uint32_t& r0, uint32_t& r1,
                                       uint32_t& r2, uint32_t& r3) {
    asm volatile("ldmatrix.sync.aligned.m8n8.x4.trans.shared.b16 {%0,%1,%2,%3}, [%4];"
                 : "=r"(r0), "=r"(r1), "=r"(r2), "=r"(r3) : "r"(addr));
}
__device__ __forceinline__ void mma_bf16(float* c, const uint32_t* a, const uint32_t* b) {
    asm volatile("mma.sync.aligned.m16n8k16.row.col.f32.bf16.bf16.f32 "
                 "{%0,%1,%2,%3}, {%4,%5,%6,%7}, {%8,%9}, {%0,%1,%2,%3};"
                 : "+f"(c[0]), "+f"(c[1]), "+f"(c[2]), "+f"(c[3])
                 : "r"(a[0]), "r"(a[1]), "r"(a[2]), "r"(a[3]), "r"(b[0]), "r"(b[1]));
}
__device__ __forceinline__ float ex2(float x) {
    float y; asm("ex2.approx.f32 %0, %1;" : "=f"(y) : "f"(x)); return y;
}
__device__ __forceinline__ uint32_t pack2(bf16 a, bf16 b) {
    __nv_bfloat162 p; p.x = a; p.y = b;
    return *(uint32_t*)&p;
}
// 128B-row swizzle (BK=64): 8 16B cols, XOR by row&7 (SW128)
__device__ __forceinline__ uint32_t sw128r(int row, int c) {
    return (uint32_t)(row * 128 + ((c ^ (row & 7)) << 4));
}

// ---------------------------------------------------------------------------
// Tensor-core GEMM via mma.sync bf16, 128x128 block tile, BK=64, 1-pass,
// 3-stage cp.async pipeline, 2 CTAs/SM. gridDim.z == 2 -> blockIdx.z picks
// second weight/bias/output set (used to fuse Q and K).
// stage (32KB): [Ah 16K][Bh 16K] (128B rows, sw128r)
// EPI: 1 = bias*scl + R -> fp32 ; 2 = bias*scl + leaky -> bf16 hi ;
//      4 = bias*scl -> bf16 hi
// ---------------------------------------------------------------------------
constexpr int GSTAGE = 32768;
constexpr int GSMEM  = 3 * GSTAGE;   // 98304

template<int EPI, bool CONV>
__global__ __launch_bounds__(256, 2)
void gemm_tc(const bf16* __restrict__ Ah, int ldA,
             const bf16* Bh_, int ldB,
             int Ktap, int ntaps, int tapbase, float scl_,
             const float* bias_, const float* __restrict__ R,
             float* __restrict__ Cf, bf16* Ch_, int Nt,
             const bf16* Bh2, const float* bias2, float scl2, bf16* Ch2)
{
    extern __shared__ char smem[];
    const uint32_t sbase = smem_to_u32(smem);
    const int tid = threadIdx.x, wid = tid >> 5, lane = tid & 31;
    const int m0 = blockIdx.y * 128, n0 = blockIdx.x * 128;

    const bf16* Bh = Bh_;
    const float* bias = bias_;  float scl = scl_;
    bf16* Ch = Ch_;
    if (blockIdx.z == 1) { Bh = Bh2; bias = bias2; scl = scl2; Ch = Ch2; }

    int rowbase;
    if (CONV) { const int bn = m0 >> 8; const int t0 = m0 & 255; rowbase = bn * SP + t0 + tapbase; }
    else      { rowbase = m0; }

    const int kcpt = Ktap >> 6;          // 64-wide chunks per tap
    const int nch  = ntaps * kcpt;
    const int c8   = tid & 7;            // 16B col 0..7
    const int rw   = tid >> 3;           // row 0..31

    auto load_chunk = [&](int c, int stage) {
        const int tap = c / kcpt;
        const int kt  = (c - tap * kcpt) << 6;
        const size_t aoff = (size_t)(rowbase + tap) * ldA + kt + c8 * 8;
        const size_t boff = (size_t)n0 * ldB + (size_t)tap * Ktap + kt + c8 * 8;
        const uint32_t st = sbase + stage * GSTAGE;
#pragma unroll
        for (int i = 0; i < 4; i++) {
            const int row = rw + i * 32;
            const uint32_t so = sw128r(row, c8);
            CP_ASYNC16(st +         so, Ah + aoff + (size_t)row * ldA);
            CP_ASYNC16(st + 16384 + so, Bh + boff + (size_t)row * ldB);
        }
        CP_ASYNC_COMMIT();
    };

    load_chunk(0, 0);
    load_chunk(1, 1);

    const int wm  = wid & 1,  wn  = wid >> 1;
    const int m0w = wm * 64,  n0w = wn * 32;
    const int tq  = lane >> 3, rin = lane & 7;
    const int aRow = m0w + (tq & 1) * 8 + rin;
    const int akh  = tq >> 1;
    const int bRow = n0w + (tq >> 1) * 8 + rin;
    const int bkh  = tq & 1;

    float acc[4][4][4];
#pragma unroll
    for (int i = 0; i < 4; i++)
#pragma unroll
        for (int j = 0; j < 4; j++)
#pragma unroll
            for (int r = 0; r < 4; r++) acc[i][j][r] = 0.f;

    for (int c = 0; c < nch; c++) {
        if (c + 1 < nch) asm volatile("cp.async.wait_group 1;" ::: "memory");
        else             asm volatile("cp.async.wait_group 0;" ::: "memory");
        __syncthreads();
        if (c + 2 < nch) load_chunk(c + 2, (c + 2) % 3);

        const uint32_t Ab = sbase + (c % 3) * GSTAGE;
        const uint32_t Bb = Ab + 16384;

#pragma unroll
        for (int ks = 0; ks < 4; ks++) {
            uint32_t ah[4][4], bh[4][2];
#pragma unroll
            for (int mt = 0; mt < 4; mt++) {
                const int r = aRow + mt * 16;   // r & 7 == rin
                const uint32_t ad = Ab + (uint32_t)(r * 128)
                                  + (uint32_t)((((ks * 2 + akh) ^ rin) & 7) << 4);
                ldsm4(ad, ah[mt][0], ah[mt][1], ah[mt][2], ah[mt][3]);
            }
#pragma unroll
            for (int nt2 = 0; nt2 < 2; nt2++) {
                const int r = bRow + nt2 * 16;  // r & 7 == rin
                const uint32_t bd = Bb + (uint32_t)(r * 128)
                                  + (uint32_t)((((ks * 2 + bkh) ^ rin) & 7) << 4);
                uint32_t r0, r1, r2, r3;
                ldsm4(bd, r0, r1, r2, r3);
                bh[nt2 * 2][0] = r0; bh[nt2 * 2][1] = r1;
                bh[nt2 * 2 + 1][0] = r2; bh[nt2 * 2 + 1][1] = r3;
            }
#pragma unroll
            for (int mt = 0; mt < 4; mt++)
#pragma unroll
                for (int nt = 0; nt < 4; nt++)
                    mma_bf16(acc[mt][nt], ah[mt], bh[nt]);
        }
    }

    const int erow = lane >> 2;
    const int ecol = (lane & 3) * 2;
#pragma unroll
    for (int mt = 0; mt < 4; mt++) {
#pragma unroll
        for (int nt = 0; nt < 4; nt++) {
            const int col = n0 + n0w + nt * 8 + ecol;
            const float2 bi = *(const float2*)&bias[col];
#pragma unroll
            for (int half = 0; half < 2; half++) {
                const int row = m0 + m0w + mt * 16 + erow + half * 8;
                float v0 = (acc[mt][nt][half * 2 + 0] + bi.x) * scl;
                float v1 = (acc[mt][nt][half * 2 + 1] + bi.y) * scl;
                if (EPI == 1) {
                    const float2 rr = *(const float2*)&R[(size_t)row * Nt + col];
                    v0 += rr.x; v1 += rr.y;
                    float2 o; o.x = v0; o.y = v1;
                    *(float2*)&Cf[(size_t)row * Nt + col] = o;
                } else {
                    if (EPI == 2) {
                        v0 = v0 > 0.f ? v0 : 0.01f * v0;
                        v1 = v1 > 0.f ? v1 : 0.01f * v1;
                    }
                    *(uint32_t*)&Ch[(size_t)row * Nt + col] =
                        pack2(__float2bfloat16(v0), __float2bfloat16(v1));
                }
            }
        }
    }
}

// ---------------------------------------------------------------------------
// pad + convert x into bf16 padded buffer [bn][258][256]
// ---------------------------------------------------------------------------
__global__ __launch_bounds__(256)
void padcvt_x(const float* __restrict__ x, bf16* __restrict__ xh)
{
    const size_t i = (size_t)blockIdx.x * 256 + threadIdx.x;
    const int d = (int)(i & 255);
    const size_t rest = i >> 8;
    const int t = (int)(rest % SP);
    const size_t bn = rest / SP;
    float v = 0.f;
    if (t >= 1 && t <= S2) v = x[(bn * S2 + (t - 1)) * D + d];
    xh[i] = __float2bfloat16(v);
}

// ---------------------------------------------------------------------------
// fused weight transpose+convert (hi only): 6 weights in one launch
// ---------------------------------------------------------------------------
__global__ __launch_bounds__(256)
void wtall(const float* __restrict__ Wq, const float* __restrict__ Wk,
           const float* __restrict__ Wv, const float* __restrict__ Wo,
           const float* __restrict__ W1, const float* __restrict__ W2,
           bf16* wqh, bf16* wkh, bf16* wvh, bf16* woh, bf16* w1h, bf16* w2h)
{
    __shared__ float ts[32][33];
    const int t = blockIdx.x;
    const float* W; bf16* Bh; int K, N, lt;
    if      (t < 192) { W = Wq; Bh = wqh; K = 768;  N = 256;  lt = t; }
    else if (t < 384) { W = Wk; Bh = wkh; K = 768;  N = 256;  lt = t - 192; }
    else if (t < 448) { W = Wv; Bh = wvh; K = 256;  N = 256;  lt = t - 384; }
    else if (t < 512) { W = Wo; Bh = woh; K = 256;  N = 256;  lt = t - 448; }
    else if (t < 768) { W = W1; Bh = w1h; K = 256;  N = 1024; lt = t - 512; }
    else              { W = W2; Bh = w2h; K = 1024; N = 256;  lt = t - 768; }
    const int ntn = N / 32;
    const int n0 = (lt % ntn) * 32, k0 = (lt / ntn) * 32;
    const int tx = threadIdx.x, ty = threadIdx.y;   // 32 x 8
#pragma unroll
    for (int j = 0; j < 4; j++)
        ts[ty + j * 8][tx] = W[(size_t)(k0 + ty + j * 8) * N + n0 + tx];
    __syncthreads();
#pragma unroll
    for (int j = 0; j < 4; j++)
        Bh[(size_t)(n0 + ty + j * 8) * K + k0 + tx] = __float2bfloat16(ts[tx][ty + j * 8]);
}

// ---------------------------------------------------------------------------
// Flash attention on tensor cores, single-pass bf16, base-2 softmax
// (q pre-scaled by log2(e)/sqrt(HD); exp -> single ex2.approx).
// One block per (b,n,h); 8 warps x 32 rows. V B-frags via ldmatrix.x4.trans.
// smem: Qh Kh Vh, 3 x 20480 (rows stride 80B -> conflict-free)
// ---------------------------------------------------------------------------
constexpr int ATT_SMEM = 3 * 20480;   // 61440

__global__ __launch_bounds__(256, 2)
void attn_tc(const bf16* __restrict__ qh, const bf16* __restrict__ kh,
             const bf16* __restrict__ vh, bf16* __restrict__ oh)
{
    extern __shared__ char smem[];
    const uint32_t sb = smem_to_u32(smem);
    const uint32_t Qh = sb, Kh = sb + 20480, Vh = sb + 40960;

    const int tid = threadIdx.x, wid = tid >> 5, lane = tid & 31;
    const int h = blockIdx.x & 7, bn = blockIdx.x >> 3;
    const size_t gbase = (size_t)bn * 256 * 256 + h * 32;

    for (int idx = tid; idx < 1024; idx += 256) {
        const int row = idx >> 2, c = idx & 3;
        const size_t g = gbase + (size_t)row * 256 + c * 8;
        const uint32_t so = row * 80 + c * 16;
        CP_ASYNC16(Qh + so, qh + g);
        CP_ASYNC16(Kh + so, kh + g);
        CP_ASYNC16(Vh + so, vh + g);
    }
    CP_ASYNC_COMMIT();
    asm volatile("cp.async.wait_group 0;" ::: "memory");
    __syncthreads();

    const int tq = lane >> 3, rin = lane & 7;
    const int aR  = (tq & 1) * 8 + rin;
    const int akh = tq >> 1;
    const int bR  = (tq >> 1) * 8 + rin;
    const int bkh = tq & 1;
    const int vrow  = (lane & 7) + ((lane >> 3) & 1) * 8;
    const int vcolb = ((lane >> 4) & 1) * 16;

    uint32_t qf[2][2][4];
#pragma unroll
    for (int mt = 0; mt < 2; mt++)
#pragma unroll
        for (int ks = 0; ks < 2; ks++) {
            const uint32_t ad = Qh + (uint32_t)((wid * 32 + mt * 16 + aR) * 80)
                              + (uint32_t)((ks * 2 + akh) * 16);
            ldsm4(ad, qf[mt][ks][0], qf[mt][ks][1], qf[mt][ks][2], qf[mt][ks][3]);
        }

    float O[2][4][4];
#pragma unroll
    for (int mt = 0; mt < 2; mt++)
#pragma unroll
        for (int j = 0; j < 4; j++)
#pragma unroll
            for (int r = 0; r < 4; r++) O[mt][j][r] = 0.f;
    float mrow[2][2] = { {-1e30f, -1e30f}, {-1e30f, -1e30f} };
    float lrow[2][2] = { {0.f, 0.f}, {0.f, 0.f} };

    for (int s0 = 0; s0 < 256; s0 += 64) {
        float acc[2][8][4];
#pragma unroll
        for (int mt = 0; mt < 2; mt++)
#pragma unroll
            for (int j = 0; j < 8; j++)
#pragma unroll
                for (int r = 0; r < 4; r++) acc[mt][j][r] = 0.f;

#pragma unroll
        for (int ks = 0; ks < 2; ks++) {
            uint32_t kb[8][2];
#pragma unroll
            for (int g = 0; g < 4; g++) {
                const uint32_t kd = Kh + (uint32_t)((s0 + g * 16 + bR) * 80)
                                  + (uint32_t)((ks * 2 + bkh) * 16);
                uint32_t r0, r1, r2, r3;
                ldsm4(kd, r0, r1, r2, r3);
                kb[g * 2][0] = r0; kb[g * 2][1] = r1;
                kb[g * 2 + 1][0] = r2; kb[g * 2 + 1][1] = r3;
            }
#pragma unroll
            for (int mt = 0; mt < 2; mt++)
#pragma unroll
                for (int j = 0; j < 8; j++)
                    mma_bf16(acc[mt][j], qf[mt][ks], kb[j]);
        }

#pragma unroll
        for (int mt = 0; mt < 2; mt++) {
            float mxA = -1e30f, mxB = -1e30f;
#pragma unroll
            for (int j = 0; j < 8; j++) {
                mxA = fmaxf(mxA, fmaxf(acc[mt][j][0], acc[mt][j][1]));
                mxB = fmaxf(mxB, fmaxf(acc[mt][j][2], acc[mt][j][3]));
            }
            mxA = fmaxf(mxA, __shfl_xor_sync(0xffffffffu, mxA, 1));
            mxA = fmaxf(mxA, __shfl_xor_sync(0xffffffffu, mxA, 2));
            mxB = fmaxf(mxB, __shfl_xor_sync(0xffffffffu, mxB, 1));
            mxB = fmaxf(mxB, __shfl_xor_sync(0xffffffffu, mxB, 2));
            const float mnA = fmaxf(mrow[mt][0], mxA);
            const float mnB = fmaxf(mrow[mt][1], mxB);
            const float fA = ex2(mrow[mt][0] - mnA);
            const float fB = ex2(mrow[mt][1] - mnB);
            mrow[mt][0] = mnA; mrow[mt][1] = mnB;
            float sA = 0.f, sB = 0.f;
#pragma unroll
            for (int j = 0; j < 8; j++) {
                acc[mt][j][0] = ex2(acc[mt][j][0] - mnA);
                acc[mt][j][1] = ex2(acc[mt][j][1] - mnA);
                acc[mt][j][2] = ex2(acc[mt][j][2] - mnB);
                acc[mt][j][3] = ex2(acc[mt][j][3] - mnB);
                sA += acc[mt][j][0] + acc[mt][j][1];
                sB += acc[mt][j][2] + acc[mt][j][3];
            }
            lrow[mt][0] = lrow[mt][0] * fA + sA;
            lrow[mt][1] = lrow[mt][1] * fB + sB;
#pragma unroll
            for (int j = 0; j < 4; j++) {
                O[mt][j][0] *= fA; O[mt][j][1] *= fA;
                O[mt][j][2] *= fB; O[mt][j][3] *= fB;
            }
        }

#pragma unroll
        for (int kt = 0; kt < 4; kt++) {
            uint32_t vb[4][2];
#pragma unroll
            for (int nb = 0; nb < 2; nb++) {
                const uint32_t vd = Vh + (uint32_t)((s0 + kt * 16 + vrow) * 80)
                                  + (uint32_t)(nb * 32 + vcolb);
                uint32_t r0, r1, r2, r3;
                ldsm4t(vd, r0, r1, r2, r3);
                vb[nb * 2][0] = r0; vb[nb * 2][1] = r1;
                vb[nb * 2 + 1][0] = r2; vb[nb * 2 + 1][1] = r3;
            }
#pragma unroll
            for (int mt = 0; mt < 2; mt++) {
                uint32_t ph[4];
#pragma unroll
                for (int half = 0; half < 2; half++) {
                    const int j = 2 * kt + half;
                    ph[half * 2 + 0] = pack2(__float2bfloat16(acc[mt][j][0]),
                                             __float2bfloat16(acc[mt][j][1]));
                    ph[half * 2 + 1] = pack2(__float2bfloat16(acc[mt][j][2]),
                                             __float2bfloat16(acc[mt][j][3]));
                }
#pragma unroll
                for (int j2 = 0; j2 < 4; j2++)
                    mma_bf16(O[mt][j2], ph, vb[j2]);
            }
        }
    }

#pragma unroll
    for (int mt = 0; mt < 2; mt++) {
        float lA = lrow[mt][0], lB = lrow[mt][1];
        lA += __shfl_xor_sync(0xffffffffu, lA, 1);
        lA += __shfl_xor_sync(0xffffffffu, lA, 2);
        lB += __shfl_xor_sync(0xffffffffu, lB, 1);
        lB += __shfl_xor_sync(0xffffffffu, lB, 2);
        const float invA = 1.f / lA, invB = 1.f / lB;
        const int rowA = wid * 32 + mt * 16 + (lane >> 2);
        const size_t gA = gbase + (size_t)rowA * 256;
        const size_t gB = gA + (size_t)8 * 256;
#pragma unroll
        for (int j2 = 0; j2 < 4; j2++) {
            const int col = j2 * 8 + (lane & 3) * 2;
            *(uint32_t*)&oh[gA + col] = pack2(__float2bfloat16(O[mt][j2][0] * invA),
                                              __float2bfloat16(O[mt][j2][1] * invA));
            *(uint32_t*)&oh[gB + col] = pack2(__float2bfloat16(O[mt][j2][2] * invB),
                                              __float2bfloat16(O[mt][j2][3] * invB));
        }
    }
}

// ---------------------------------------------------------------------------
// LayerNorm (D=256). Optionally emits bf16 hi of the normalized output.
// ---------------------------------------------------------------------------
template<bool EMIT>
__global__ __launch_bounds__(256)
void ln_k(const float* __restrict__ X, const float* __restrict__ g,
          const float* __restrict__ be, float* __restrict__ Y,
          bf16* __restrict__ Yh)
{
    const int r    = blockIdx.x * 8 + (threadIdx.x >> 5);
    const int lane = threadIdx.x & 31;
    const float* xr = X + (long long)r * D;

    float xv[8];
    float s = 0.f, ss = 0.f;
#pragma unroll
    for (int j = 0; j < 8; j++) {
        const float t = xr[lane + j * 32];
        xv[j] = t; s += t; ss += t * t;
    }
#pragma unroll
    for (int ofs = 16; ofs > 0; ofs >>= 1) {
        s  += __shfl_xor_sync(0xffffffffu, s,  ofs);
        ss += __shfl_xor_sync(0xffffffffu, ss, ofs);
    }
    const float mu  = s * (1.f / 256.f);
    const float var = ss * (1.f / 256.f) - mu * mu;
    const float rs  = rsqrtf(var + 1e-5f);

#pragma unroll
    for (int j = 0; j < 8; j++) {
        const int d = lane + j * 32;
        const float y = (xv[j] - mu) * rs * g[d] + be[d];
        Y[(long long)r * D + d] = y;
        if (EMIT) Yh[(long long)r * D + d] = __float2bfloat16(y);
    }
}

// ---------------------------------------------------------------------------
extern "C" void kernel_launch(void* const* d_in, const int* in_sizes, int n_in,
                              void* d_out, int out_size)
{
    const float* x   = (const float*)d_in[0];
    const float* Wq  = (const float*)d_in[1];
    const float* bq  = (const float*)d_in[2];
    const float* Wk  = (const float*)d_in[3];
    const float* bk  = (const float*)d_in[4];
    const float* Wv  = (const float*)d_in[5];
    const float* bv  = (const float*)d_in[6];
    const float* Wo  = (const float*)d_in[7];
    const float* bo  = (const float*)d_in[8];
    const float* W1  = (const float*)d_in[9];
    const float* b1  = (const float*)d_in[10];
    const float* W2  = (const float*)d_in[11];
    const float* b2  = (const float*)d_in[12];
    const float* g1  = (const float*)d_in[13];
    const float* be1 = (const float*)d_in[14];
    const float* g2  = (const float*)d_in[15];
    const float* be2 = (const float*)d_in[16];
    float* out = (float*)d_out;

    bf16 *xph, *qh, *kh, *vh, *aoh, *hh, *ffh;
    bf16 *wqh, *wkh, *wvh, *woh, *w1h, *w2h;
    float *sb, *hbuf;
    cudaGetSymbolAddress((void**)&xph, g_xph);
    cudaGetSymbolAddress((void**)&qh,  g_qh);  cudaGetSymbolAddress((void**)&kh,  g_kh);
    cudaGetSymbolAddress((void**)&vh,  g_vh);  cudaGetSymbolAddress((void**)&aoh, g_aoh);
    cudaGetSymbolAddress((void**)&sb,  g_s);   cudaGetSymbolAddress((void**)&hbuf, g_h);
    cudaGetSymbolAddress((void**)&hh,  g_hh);  cudaGetSymbolAddress((void**)&ffh, g_ffh);
    cudaGetSymbolAddress((void**)&wqh, g_wqh); cudaGetSymbolAddress((void**)&wkh, g_wkh);
    cudaGetSymbolAddress((void**)&wvh, g_wvh); cudaGetSymbolAddress((void**)&woh, g_woh);
    cudaGetSymbolAddress((void**)&w1h, g_w1h); cudaGetSymbolAddress((void**)&w2h, g_w2h);

    cudaFuncSetAttribute(gemm_tc<4, true>,  cudaFuncAttributeMaxDynamicSharedMemorySize, GSMEM);
    cudaFuncSetAttribute(gemm_tc<1, false>, cudaFuncAttributeMaxDynamicSharedMemorySize, GSMEM);
    cudaFuncSetAttribute(gemm_tc<2, false>, cudaFuncAttributeMaxDynamicSharedMemorySize, GSMEM);
    cudaFuncSetAttribute(attn_tc, cudaFuncAttributeMaxDynamicSharedMemorySize, ATT_SMEM);

    padcvt_x<<<(BN_ * SP * D) / 256, 256>>>(x, xph);
    wtall<<<1024, dim3(32, 8)>>>(Wq, Wk, Wv, Wo, W1, W2, wqh, wkh, wvh, woh, w1h, w2h);

    const dim3 gQK(D / 128, TOK / 128, 2);
    const dim3 gD (D / 128, TOK / 128);
    const dim3 gF (Fd / 128, TOK / 128);
    // q pre-scaled by log2(e)/sqrt(32) for base-2 softmax (ex2)
    const float qscale = 0.2550663527668625f;

    // Q+K fused (3-tap conv, 1-pass, BK=64, hi out; Q pre-scaled; ldB = 3*D)
    gemm_tc<4, true><<<gQK, 256, GSMEM>>>(xph, D, wqh, 3 * D, D, 3, 0, qscale,
                                          bq, nullptr, nullptr, qh, D,
                                          wkh, bk, 1.f, kh);
    // V (1-pass, BK=64, hi out; center tap)
    gemm_tc<4, true><<<gD, 256, GSMEM>>>(xph, D, wvh, D, D, 1, 1, 1.f,
                                         bv, nullptr, nullptr, vh, D,
                                         nullptr, nullptr, 0.f, nullptr);
    // attention (single-pass bf16, base-2 softmax)
    attn_tc<<<Bd * S1 * Hh, 256, ATT_SMEM>>>(qh, kh, vh, aoh);
    // s = x + ao@Wo + bo
    gemm_tc<1, false><<<gD, 256, GSMEM>>>(aoh, D, woh, D, D, 1, 0, 1.f,
                                          bo, x, sb, nullptr, D,
                                          nullptr, nullptr, 0.f, nullptr);
    ln_k<true><<<TOK / 8, 256>>>(sb, g1, be1, hbuf, hh);
    // ff = leaky(h@W1 + b1)
    gemm_tc<2, false><<<gF, 256, GSMEM>>>(hh, D, w1h, D, D, 1, 0, 1.f,
                                          b1, nullptr, nullptr, ffh, Fd,
                                          nullptr, nullptr, 0.f, nullptr);
    // s = h + ff@W2 + b2
    gemm_tc<1, false><<<gD, 256, GSMEM>>>(ffh, Fd, w2h, Fd, Fd, 1, 0, 1.f,
                                          b2, hbuf, sb, nullptr, D,
                                          nullptr, nullptr, 0.f, nullptr);
    ln_k<false><<<TOK / 8, 256>>>(sb, g2, be2, out, nullptr);
}

// round 17
// speedup vs baseline: 1.1189x; 1.0016x over previous
#include <cuda_runtime.h>
#include <cuda_bf16.h>
#include <cstdint>
#include <math.h>

using bf16 = __nv_bfloat16;

// ---------------- problem constants ----------------
constexpr int Bd  = 4;
constexpr int S1  = 64;
constexpr int S2  = 256;
constexpr int D   = 256;
constexpr int Hh  = 8;
constexpr int HD  = 32;
constexpr int Fd  = 1024;
constexpr int TOK = Bd * S1 * S2;     // 65536
constexpr int BN_ = Bd * S1;          // 256
constexpr int SP  = S2 + 2;           // padded time length 258

// ---------------- scratch (device globals) ----------------
__device__ bf16  g_xph[BN_ * SP * D];
__device__ bf16  g_qh [TOK * D];
__device__ bf16  g_kh [TOK * D];
__device__ bf16  g_vh [TOK * D];
__device__ bf16  g_aoh[TOK * D];
__device__ float g_s  [TOK * D];
__device__ float g_h  [TOK * D];
__device__ bf16  g_hh [TOK * D];
__device__ bf16  g_ffh[TOK * Fd];
// transposed weights (hi only)
__device__ bf16 g_wqh[D * 3 * D];
__device__ bf16 g_wkh[D * 3 * D];
__device__ bf16 g_wvh[D * D];
__device__ bf16 g_woh[D * D];
__device__ bf16 g_w1h[Fd * D];
__device__ bf16 g_w2h[D * Fd];

// ---------------- helpers ----------------
__device__ __forceinline__ uint32_t smem_to_u32(const void* p) {
    uint32_t a;
    asm("{ .reg .u64 t; cvta.to.shared.u64 t, %1; cvt.u32.u64 %0, t; }" : "=r"(a) : "l"(p));
    return a;
}
#define CP_ASYNC16(s, g) \
    asm volatile("cp.async.cg.shared.global [%0], [%1], 16;" :: "r"((uint32_t)(s)), "l"(g))
#define CP_ASYNC_COMMIT() asm volatile("cp.async.commit_group;" ::: "memory")

__device__ __forceinline__ void ldsm4(uint32_t addr, uint32_t& r0, uint32_t& r1,
                                      uint32_t& r2, uint32_t& r3) {
    asm volatile("ldmatrix.sync.aligned.m8n8.x4.shared.b16 {%0,%1,%2,%3}, [%4];"
                 : "=r"(r0), "=r"(r1), "=r"(r2), "=r"(r3) : "r"(addr));
}
__device__ __forceinline__ void ldsm4t(uint32_t addr, uint32_t& r0, uint32_t& r1,
                                       uint32_t& r2, uint32_t& r3) {
    asm volatile("ldmatrix.sync.aligned.m8n8.x4.trans.shared.b16 {%0,%1,%2,%3}, [%4];"
                 : "=r"(r0), "=r"(r1), "=r"(r2), "=r"(r3) : "r"(addr));
}
__device__ __forceinline__ void mma_bf16(float* c, const uint32_t* a, const uint32_t* b) {
    asm volatile("mma.sync.aligned.m16n8k16.row.col.f32.bf16.bf16.f32 "
                 "{%0,%1,%2,%3}, {%4,%5,%6,%7}, {%8,%9}, {%0,%1,%2,%3};"
                 : "+f"(c[0]), "+f"(c[1]), "+f"(c[2]), "+f"(c[3])
                 : "r"(a[0]), "r"(a[1]), "r"(a[2]), "r"(a[3]), "r"(b[0]), "r"(b[1]));
}
__device__ __forceinline__ float ex2(float x) {
    float y; asm("ex2.approx.f32 %0, %1;" : "=f"(y) : "f"(x)); return y;
}
__device__ __forceinline__ uint32_t pack2(bf16 a, bf16 b) {
    __nv_bfloat162 p; p.x = a; p.y = b;
    return *(uint32_t*)&p;
}
// 128B-row swizzle (BK=64): 8 16B cols, XOR by row&7 (SW128)
__device__ __forceinline__ uint32_t sw128r(int row, int c) {
    return (uint32_t)(row * 128 + ((c ^ (row & 7)) << 4));
}

// ---------------------------------------------------------------------------
// Tensor-core GEMM via mma.sync bf16, 128x128 block tile, BK=64, 1-pass,
// 3-stage cp.async pipeline, 2 CTAs/SM. gridDim.z == 2 -> blockIdx.z picks
// second weight/bias/output set (used to fuse Q and K).
// stage (32KB): [Ah 16K][Bh 16K] (128B rows, sw128r)
// EPI: 1 = bias*scl + R -> fp32 ; 2 = bias*scl + leaky -> bf16 hi ;
//      4 = bias*scl -> bf16 hi
// ---------------------------------------------------------------------------
constexpr int GSTAGE = 32768;
constexpr int GSMEM  = 3 * GSTAGE;   // 98304

template<int EPI, bool CONV>
__global__ __launch_bounds__(256, 2)
void gemm_tc(const bf16* __restrict__ Ah, int ldA,
             const bf16* Bh_, int ldB,
             int Ktap, int ntaps, int tapbase, float scl_,
             const float* bias_, const float* __restrict__ R,
             float* __restrict__ Cf, bf16* Ch_, int Nt,
             const bf16* Bh2, const float* bias2, float scl2, bf16* Ch2)
{
    extern __shared__ char smem[];
    const uint32_t sbase = smem_to_u32(smem);
    const int tid = threadIdx.x, wid = tid >> 5, lane = tid & 31;
    const int m0 = blockIdx.y * 128, n0 = blockIdx.x * 128;

    const bf16* Bh = Bh_;
    const float* bias = bias_;  float scl = scl_;
    bf16* Ch = Ch_;
    if (blockIdx.z == 1) { Bh = Bh2; bias = bias2; scl = scl2; Ch = Ch2; }

    int rowbase;
    if (CONV) { const int bn = m0 >> 8; const int t0 = m0 & 255; rowbase = bn * SP + t0 + tapbase; }
    else      { rowbase = m0; }

    const int kcpt = Ktap >> 6;          // 64-wide chunks per tap
    const int nch  = ntaps * kcpt;
    const int c8   = tid & 7;            // 16B col 0..7
    const int rw   = tid >> 3;           // row 0..31

    auto load_chunk = [&](int c, int stage) {
        const int tap = c / kcpt;
        const int kt  = (c - tap * kcpt) << 6;
        const size_t aoff = (size_t)(rowbase + tap) * ldA + kt + c8 * 8;
        const size_t boff = (size_t)n0 * ldB + (size_t)tap * Ktap + kt + c8 * 8;
        const uint32_t st = sbase + stage * GSTAGE;
#pragma unroll
        for (int i = 0; i < 4; i++) {
            const int row = rw + i * 32;
            const uint32_t so = sw128r(row, c8);
            CP_ASYNC16(st +         so, Ah + aoff + (size_t)row * ldA);
            CP_ASYNC16(st + 16384 + so, Bh + boff + (size_t)row * ldB);
        }
        CP_ASYNC_COMMIT();
    };

    load_chunk(0, 0);
    load_chunk(1, 1);

    const int wm  = wid & 1,  wn  = wid >> 1;
    const int m0w = wm * 64,  n0w = wn * 32;
    const int tq  = lane >> 3, rin = lane & 7;
    const int aRow = m0w + (tq & 1) * 8 + rin;
    const int akh  = tq >> 1;
    const int bRow = n0w + (tq >> 1) * 8 + rin;
    const int bkh  = tq & 1;

    float acc[4][4][4];
#pragma unroll
    for (int i = 0; i < 4; i++)
#pragma unroll
        for (int j = 0; j < 4; j++)
#pragma unroll
            for (int r = 0; r < 4; r++) acc[i][j][r] = 0.f;

    for (int c = 0; c < nch; c++) {
        if (c + 1 < nch) asm volatile("cp.async.wait_group 1;" ::: "memory");
        else             asm volatile("cp.async.wait_group 0;" ::: "memory");
        __syncthreads();
        if (c + 2 < nch) load_chunk(c + 2, (c + 2) % 3);

        const uint32_t Ab = sbase + (c % 3) * GSTAGE;
        const uint32_t Bb = Ab + 16384;

#pragma unroll
        for (int ks = 0; ks < 4; ks++) {
            uint32_t ah[4][4], bh[4][2];
#pragma unroll
            for (int mt = 0; mt < 4; mt++) {
                const int r = aRow + mt * 16;   // r & 7 == rin
                const uint32_t ad = Ab + (uint32_t)(r * 128)
                                  + (uint32_t)((((ks * 2 + akh) ^ rin) & 7) << 4);
                ldsm4(ad, ah[mt][0], ah[mt][1], ah[mt][2], ah[mt][3]);
            }
#pragma unroll
            for (int nt2 = 0; nt2 < 2; nt2++) {
                const int r = bRow + nt2 * 16;  // r & 7 == rin
                const uint32_t bd = Bb + (uint32_t)(r * 128)
                                  + (uint32_t)((((ks * 2 + bkh) ^ rin) & 7) << 4);
                uint32_t r0, r1, r2, r3;
                ldsm4(bd, r0, r1, r2, r3);
                bh[nt2 * 2][0] = r0; bh[nt2 * 2][1] = r1;
                bh[nt2 * 2 + 1][0] = r2; bh[nt2 * 2 + 1][1] = r3;
            }
#pragma unroll
            for (int mt = 0; mt < 4; mt++)
#pragma unroll
                for (int nt = 0; nt < 4; nt++)
                    mma_bf16(acc[mt][nt], ah[mt], bh[nt]);
        }
    }

    const int erow = lane >> 2;
    const int ecol = (lane & 3) * 2;
#pragma unroll
    for (int mt = 0; mt < 4; mt++) {
#pragma unroll
        for (int nt = 0; nt < 4; nt++) {
            const int col = n0 + n0w + nt * 8 + ecol;
            const float2 bi = *(const float2*)&bias[col];
#pragma unroll
            for (int half = 0; half < 2; half++) {
                const int row = m0 + m0w + mt * 16 + erow + half * 8;
                float v0 = (acc[mt][nt][half * 2 + 0] + bi.x) * scl;
                float v1 = (acc[mt][nt][half * 2 + 1] + bi.y) * scl;
                if (EPI == 1) {
                    const float2 rr = *(const float2*)&R[(size_t)row * Nt + col];
                    v0 += rr.x; v1 += rr.y;
                    float2 o; o.x = v0; o.y = v1;
                    *(float2*)&Cf[(size_t)row * Nt + col] = o;
                } else {
                    if (EPI == 2) {
                        v0 = v0 > 0.f ? v0 : 0.01f * v0;
                        v1 = v1 > 0.f ? v1 : 0.01f * v1;
                    }
                    *(uint32_t*)&Ch[(size_t)row * Nt + col] =
                        pack2(__float2bfloat16(v0), __float2bfloat16(v1));
                }
            }
        }
    }
}

// ---------------------------------------------------------------------------
// pad + convert x into bf16 padded buffer [bn][258][256]
// ---------------------------------------------------------------------------
__global__ __launch_bounds__(256)
void padcvt_x(const float* __restrict__ x, bf16* __restrict__ xh)
{
    const size_t i = (size_t)blockIdx.x * 256 + threadIdx.x;
    const int d = (int)(i & 255);
    const size_t rest = i >> 8;
    const int t = (int)(rest % SP);
    const size_t bn = rest / SP;
    float v = 0.f;
    if (t >= 1 && t <= S2) v = x[(bn * S2 + (t - 1)) * D + d];
    xh[i] = __float2bfloat16(v);
}

// ---------------------------------------------------------------------------
// fused weight transpose+convert (hi only): 6 weights in one launch
// ---------------------------------------------------------------------------
__global__ __launch_bounds__(256)
void wtall(const float* __restrict__ Wq, const float* __restrict__ Wk,
           const float* __restrict__ Wv, const float* __restrict__ Wo,
           const float* __restrict__ W1, const float* __restrict__ W2,
           bf16* wqh, bf16* wkh, bf16* wvh, bf16* woh, bf16* w1h, bf16* w2h)
{
    __shared__ float ts[32][33];
    const int t = blockIdx.x;
    const float* W; bf16* Bh; int K, N, lt;
    if      (t < 192) { W = Wq; Bh = wqh; K = 768;  N = 256;  lt = t; }
    else if (t < 384) { W = Wk; Bh = wkh; K = 768;  N = 256;  lt = t - 192; }
    else if (t < 448) { W = Wv; Bh = wvh; K = 256;  N = 256;  lt = t - 384; }
    else if (t < 512) { W = Wo; Bh = woh; K = 256;  N = 256;  lt = t - 448; }
    else if (t < 768) { W = W1; Bh = w1h; K = 256;  N = 1024; lt = t - 512; }
    else              { W = W2; Bh = w2h; K = 1024; N = 256;  lt = t - 768; }
    const int ntn = N / 32;
    const int n0 = (lt % ntn) * 32, k0 = (lt / ntn) * 32;
    const int tx = threadIdx.x, ty = threadIdx.y;   // 32 x 8
#pragma unroll
    for (int j = 0; j < 4; j++)
        ts[ty + j * 8][tx] = W[(size_t)(k0 + ty + j * 8) * N + n0 + tx];
    __syncthreads();
#pragma unroll
    for (int j = 0; j < 4; j++)
        Bh[(size_t)(n0 + ty + j * 8) * K + k0 + tx] = __float2bfloat16(ts[tx][ty + j * 8]);
}

// ---------------------------------------------------------------------------
// Flash attention on tensor cores, single-pass bf16, base-2 softmax
// (q pre-scaled by log2(e)/sqrt(HD); exp -> single ex2.approx).
// One block per (b,n,h); 8 warps x 32 rows. V B-frags via ldmatrix.x4.trans.
// smem: Qh Kh Vh, 3 x 20480 (rows stride 80B -> conflict-free)
// ---------------------------------------------------------------------------
constexpr int ATT_SMEM = 3 * 20480;   // 61440

__global__ __launch_bounds__(256, 2)
void attn_tc(const bf16* __restrict__ qh, const bf16* __restrict__ kh,
             const bf16* __restrict__ vh, bf16* __restrict__ oh)
{
    extern __shared__ char smem[];
    const uint32_t sb = smem_to_u32(smem);
    const uint32_t Qh = sb, Kh = sb + 20480, Vh = sb + 40960;

    const int tid = threadIdx.x, wid = tid >> 5, lane = tid & 31;
    const int h = blockIdx.x & 7, bn = blockIdx.x >> 3;
    const size_t gbase = (size_t)bn * 256 * 256 + h * 32;

    for (int idx = tid; idx < 1024; idx += 256) {
        const int row = idx >> 2, c = idx & 3;
        const size_t g = gbase + (size_t)row * 256 + c * 8;
        const uint32_t so = row * 80 + c * 16;
        CP_ASYNC16(Qh + so, qh + g);
        CP_ASYNC16(Kh + so, kh + g);
        CP_ASYNC16(Vh + so, vh + g);
    }
    CP_ASYNC_COMMIT();
    asm volatile("cp.async.wait_group 0;" ::: "memory");
    __syncthreads();

    const int tq = lane >> 3, rin = lane & 7;
    const int aR  = (tq & 1) * 8 + rin;
    const int akh = tq >> 1;
    const int bR  = (tq >> 1) * 8 + rin;
    const int bkh = tq & 1;
    const int vrow  = (lane & 7) + ((lane >> 3) & 1) * 8;
    const int vcolb = ((lane >> 4) & 1) * 16;

    uint32_t qf[2][2][4];
#pragma unroll
    for (int mt = 0; mt < 2; mt++)
#pragma unroll
        for (int ks = 0; ks < 2; ks++) {
            const uint32_t ad = Qh + (uint32_t)((wid * 32 + mt * 16 + aR) * 80)
                              + (uint32_t)((ks * 2 + akh) * 16);
            ldsm4(ad, qf[mt][ks][0], qf[mt][ks][1], qf[mt][ks][2], qf[mt][ks][3]);
        }

    float O[2][4][4];
#pragma unroll
    for (int mt = 0; mt < 2; mt++)
#pragma unroll
        for (int j = 0; j < 4; j++)
#pragma unroll
            for (int r = 0; r < 4; r++) O[mt][j][r] = 0.f;
    float mrow[2][2] = { {-1e30f, -1e30f}, {-1e30f, -1e30f} };
    float lrow[2][2] = { {0.f, 0.f}, {0.f, 0.f} };

    for (int s0 = 0; s0 < 256; s0 += 64) {
        float acc[2][8][4];
#pragma unroll
        for (int mt = 0; mt < 2; mt++)
#pragma unroll
            for (int j = 0; j < 8; j++)
#pragma unroll
                for (int r = 0; r < 4; r++) acc[mt][j][r] = 0.f;

#pragma unroll
        for (int ks = 0; ks < 2; ks++) {
            uint32_t kb[8][2];
#pragma unroll
            for (int g = 0; g < 4; g++) {
                const uint32_t kd = Kh + (uint32_t)((s0 + g * 16 + bR) * 80)
                                  + (uint32_t)((ks * 2 + bkh) * 16);
                uint32_t r0, r1, r2, r3;
                ldsm4(kd, r0, r1, r2, r3);
                kb[g * 2][0] = r0; kb[g * 2][1] = r1;
                kb[g * 2 + 1][0] = r2; kb[g * 2 + 1][1] = r3;
            }
#pragma unroll
            for (int mt = 0; mt < 2; mt++)
#pragma unroll
                for (int j = 0; j < 8; j++)
                    mma_bf16(acc[mt][j], qf[mt][ks], kb[j]);
        }

#pragma unroll
        for (int mt = 0; mt < 2; mt++) {
            float mxA = -1e30f, mxB = -1e30f;
#pragma unroll
            for (int j = 0; j < 8; j++) {
                mxA = fmaxf(mxA, fmaxf(acc[mt][j][0], acc[mt][j][1]));
                mxB = fmaxf(mxB, fmaxf(acc[mt][j][2], acc[mt][j][3]));
            }
            mxA = fmaxf(mxA, __shfl_xor_sync(0xffffffffu, mxA, 1));
            mxA = fmaxf(mxA, __shfl_xor_sync(0xffffffffu, mxA, 2));
            mxB = fmaxf(mxB, __shfl_xor_sync(0xffffffffu, mxB, 1));
            mxB = fmaxf(mxB, __shfl_xor_sync(0xffffffffu, mxB, 2));
            const float mnA = fmaxf(mrow[mt][0], mxA);
            const float mnB = fmaxf(mrow[mt][1], mxB);
            const float fA = ex2(mrow[mt][0] - mnA);
            const float fB = ex2(mrow[mt][1] - mnB);
            mrow[mt][0] = mnA; mrow[mt][1] = mnB;
            float sA = 0.f, sB = 0.f;
#pragma unroll
            for (int j = 0; j < 8; j++) {
                acc[mt][j][0] = ex2(acc[mt][j][0] - mnA);
                acc[mt][j][1] = ex2(acc[mt][j][1] - mnA);
                acc[mt][j][2] = ex2(acc[mt][j][2] - mnB);
                acc[mt][j][3] = ex2(acc[mt][j][3] - mnB);
                sA += acc[mt][j][0] + acc[mt][j][1];
                sB += acc[mt][j][2] + acc[mt][j][3];
            }
            lrow[mt][0] = lrow[mt][0] * fA + sA;
            lrow[mt][1] = lrow[mt][1] * fB + sB;
#pragma unroll
            for (int j = 0; j < 4; j++) {
                O[mt][j][0] *= fA; O[mt][j][1] *= fA;
                O[mt][j][2] *= fB; O[mt][j][3] *= fB;
            }
        }

#pragma unroll
        for (int kt = 0; kt < 4; kt++) {
            uint32_t vb[4][2];
#pragma unroll
            for (int nb = 0; nb < 2; nb++) {
                const uint32_t vd = Vh + (uint32_t)((s0 + kt * 16 + vrow) * 80)
                                  + (uint32_t)(nb * 32 + vcolb);
                uint32_t r0, r1, r2, r3;
                ldsm4t(vd, r0, r1, r2, r3);
                vb[nb * 2][0] = r0; vb[nb * 2][1] = r1;
                vb[nb * 2 + 1][0] = r2; vb[nb * 2 + 1][1] = r3;
            }
#pragma unroll
            for (int mt = 0; mt < 2; mt++) {
                uint32_t ph[4];
#pragma unroll
                for (int half = 0; half < 2; half++) {
                    const int j = 2 * kt + half;
                    ph[half * 2 + 0] = pack2(__float2bfloat16(acc[mt][j][0]),
                                             __float2bfloat16(acc[mt][j][1]));
                    ph[half * 2 + 1] = pack2(__float2bfloat16(acc[mt][j][2]),
                                             __float2bfloat16(acc[mt][j][3]));
                }
#pragma unroll
                for (int j2 = 0; j2 < 4; j2++)
                    mma_bf16(O[mt][j2], ph, vb[j2]);
            }
        }
    }

#pragma unroll
    for (int mt = 0; mt < 2; mt++) {
        float lA = lrow[mt][0], lB = lrow[mt][1];
        lA += __shfl_xor_sync(0xffffffffu, lA, 1);
        lA += __shfl_xor_sync(0xffffffffu, lA, 2);
        lB += __shfl_xor_sync(0xffffffffu, lB, 1);
        lB += __shfl_xor_sync(0xffffffffu, lB, 2);
        const float invA = 1.f / lA, invB = 1.f / lB;
        const int rowA = wid * 32 + mt * 16 + (lane >> 2);
        const size_t gA = gbase + (size_t)rowA * 256;
        const size_t gB = gA + (size_t)8 * 256;
#pragma unroll
        for (int j2 = 0; j2 < 4; j2++) {
            const int col = j2 * 8 + (lane & 3) * 2;
            *(uint32_t*)&oh[gA + col] = pack2(__float2bfloat16(O[mt][j2][0] * invA),
                                              __float2bfloat16(O[mt][j2][1] * invA));
            *(uint32_t*)&oh[gB + col] = pack2(__float2bfloat16(O[mt][j2][2] * invB),
                                              __float2bfloat16(O[mt][j2][3] * invB));
        }
    }
}

// ---------------------------------------------------------------------------
// LayerNorm (D=256). Optionally emits bf16 hi of the normalized output.
// ---------------------------------------------------------------------------
template<bool EMIT>
__global__ __launch_bounds__(256)
void ln_k(const float* __restrict__ X, const float* __restrict__ g,
          const float* __restrict__ be, float* __restrict__ Y,
          bf16* __restrict__ Yh)
{
    const int r    = blockIdx.x * 8 + (threadIdx.x >> 5);
    const int lane = threadIdx.x & 31;
    const float* xr = X + (long long)r * D;

    float xv[8];
    float s = 0.f, ss = 0.f;
#pragma unroll
    for (int j = 0; j < 8; j++) {
        const float t = xr[lane + j * 32];
        xv[j] = t; s += t; ss += t * t;
    }
#pragma unroll
    for (int ofs = 16; ofs > 0; ofs >>= 1) {
        s  += __shfl_xor_sync(0xffffffffu, s,  ofs);
        ss += __shfl_xor_sync(0xffffffffu, ss, ofs);
    }
    const float mu  = s * (1.f / 256.f);
    const float var = ss * (1.f / 256.f) - mu * mu;
    const float rs  = rsqrtf(var + 1e-5f);

#pragma unroll
    for (int j = 0; j < 8; j++) {
        const int d = lane + j * 32;
        const float y = (xv[j] - mu) * rs * g[d] + be[d];
        Y[(long long)r * D + d] = y;
        if (EMIT) Yh[(long long)r * D + d] = __float2bfloat16(y);
    }
}

// ---------------------------------------------------------------------------
extern "C" void kernel_launch(void* const* d_in, const int* in_sizes, int n_in,
                              void* d_out, int out_size)
{
    const float* x   = (const float*)d_in[0];
    const float* Wq  = (const float*)d_in[1];
    const float* bq  = (const float*)d_in[2];
    const float* Wk  = (const float*)d_in[3];
    const float* bk  = (const float*)d_in[4];
    const float* Wv  = (const float*)d_in[5];
    const float* bv  = (const float*)d_in[6];
    const float* Wo  = (const float*)d_in[7];
    const float* bo  = (const float*)d_in[8];
    const float* W1  = (const float*)d_in[9];
    const float* b1  = (const float*)d_in[10];
    const float* W2  = (const float*)d_in[11];
    const float* b2  = (const float*)d_in[12];
    const float* g1  = (const float*)d_in[13];
    const float* be1 = (const float*)d_in[14];
    const float* g2  = (const float*)d_in[15];
    const float* be2 = (const float*)d_in[16];
    float* out = (float*)d_out;

    bf16 *xph, *qh, *kh, *vh, *aoh, *hh, *ffh;
    bf16 *wqh, *wkh, *wvh, *woh, *w1h, *w2h;
    float *sb, *hbuf;
    cudaGetSymbolAddress((void**)&xph, g_xph);
    cudaGetSymbolAddress((void**)&qh,  g_qh);  cudaGetSymbolAddress((void**)&kh,  g_kh);
    cudaGetSymbolAddress((void**)&vh,  g_vh);  cudaGetSymbolAddress((void**)&aoh, g_aoh);
    cudaGetSymbolAddress((void**)&sb,  g_s);   cudaGetSymbolAddress((void**)&hbuf, g_h);
    cudaGetSymbolAddress((void**)&hh,  g_hh);  cudaGetSymbolAddress((void**)&ffh, g_ffh);
    cudaGetSymbolAddress((void**)&wqh, g_wqh); cudaGetSymbolAddress((void**)&wkh, g_wkh);
    cudaGetSymbolAddress((void**)&wvh, g_wvh); cudaGetSymbolAddress((void**)&woh, g_woh);
    cudaGetSymbolAddress((void**)&w1h, g_w1h); cudaGetSymbolAddress((void**)&w2h, g_w2h);

    cudaFuncSetAttribute(gemm_tc<4, true>,  cudaFuncAttributeMaxDynamicSharedMemorySize, GSMEM);
    cudaFuncSetAttribute(gemm_tc<1, false>, cudaFuncAttributeMaxDynamicSharedMemorySize, GSMEM);
    cudaFuncSetAttribute(gemm_tc<2, false>, cudaFuncAttributeMaxDynamicSharedMemorySize, GSMEM);
    cudaFuncSetAttribute(attn_tc, cudaFuncAttributeMaxDynamicSharedMemorySize, ATT_SMEM);

    padcvt_x<<<(BN_ * SP * D) / 256, 256>>>(x, xph);
    wtall<<<1024, dim3(32, 8)>>>(Wq, Wk, Wv, Wo, W1, W2, wqh, wkh, wvh, woh, w1h, w2h);

    const dim3 gQK(D / 128, TOK / 128, 2);
    const dim3 gD (D / 128, TOK / 128);
    const dim3 gF (Fd / 128, TOK / 128);
    // q pre-scaled by log2(e)/sqrt(32) for base-2 softmax (ex2)
    const float qscale = 0.2550663527668625f;

    // Q+K fused (3-tap conv, 1-pass, BK=64, hi out; Q pre-scaled; ldB = 3*D)
    gemm_tc<4, true><<<gQK, 256, GSMEM>>>(xph, D, wqh, 3 * D, D, 3, 0, qscale,
                                          bq, nullptr, nullptr, qh, D,
                                          wkh, bk, 1.f, kh);
    // V (1-pass, BK=64, hi out; center tap)
    gemm_tc<4, true><<<gD, 256, GSMEM>>>(xph, D, wvh, D, D, 1, 1, 1.f,
                                         bv, nullptr, nullptr, vh, D,
                                         nullptr, nullptr, 0.f, nullptr);
    // attention (single-pass bf16, base-2 softmax)
    attn_tc<<<Bd * S1 * Hh, 256, ATT_SMEM>>>(qh, kh, vh, aoh);
    // s = x + ao@Wo + bo
    gemm_tc<1, false><<<gD, 256, GSMEM>>>(aoh, D, woh, D, D, 1, 0, 1.f,
                                          bo, x, sb, nullptr, D,
                                          nullptr, nullptr, 0.f, nullptr);
    ln_k<true><<<TOK / 8, 256>>>(sb, g1, be1, hbuf, hh);
    // ff = leaky(h@W1 + b1)
    gemm_tc<2, false><<<gF, 256, GSMEM>>>(hh, D, w1h, D, D, 1, 0, 1.f,
                                          b1, nullptr, nullptr, ffh, Fd,
                                          nullptr, nullptr, 0.f, nullptr);
    // s = h + ff@W2 + b2
    gemm_tc<1, false><<<gD, 256, GSMEM>>>(ffh, Fd, w2h, Fd, Fd, 1, 0, 1.f,
                                          b2, hbuf, sb, nullptr, D,
                                          nullptr, nullptr, 0.f, nullptr);
    ln_k<false><<<TOK / 8, 256>>>(sb, g2, be2, out, nullptr);
}